// round 14
// baseline (speedup 1.0000x reference)
#include <cuda_runtime.h>
#include <cuda_fp16.h>
#include <cstdint>
#include <math.h>

// ===========================================================================
// BertBiAttention on GB300 (sm_103 ptxas target -> mma.sync HMMA everywhere)
//   B=16, S1=256, S2=512, V_HID=1024, T_HID=768, BI_HID=1024, H=8, D=128
// Round 14: fused flash-style attention (scores + softmax + P@V in ONE
//   kernel; no fp32 score buffer, no P buffer, no softmax/ctx kernels).
//   QKV path unchanged from R13 (fp16 single-pass, merged 6-GEMM launch).
//   6 launches total.
// ===========================================================================

#define BB   16
#define SS1  256
#define SS2  512
#define HH   8
#define DD   128
#define HD   1024
#define C1_ELEMS ((size_t)BB * SS2 * HD)

typedef __half hf;

#define PADK 40
#define NSTAGE 4
#define TILEB (128 * PADK * 2)          // 10240 bytes per tile
#define SMEM_DYN (2 * NSTAGE * TILEB)   // 81920 bytes (QKV GEMM)

// fused attention smem layout (bytes)
#define FA_RING  0                       // 4 * 10240 = 40960
#define FA_Q     40960                   // 32 x 136 fp16 = 8704
#define FA_P     (40960 + 8704)          // 32 x 520 fp16 = 33280 (max Sk=512)
#define FA_RED   (FA_P + 33280)          // 32 x 4 fp32 = 512
#define FA_MASK  (FA_RED + 512)          // 512 fp32 = 2048
#define FA_SMEM  (FA_MASK + 2048)        // 85504

// ---------------- scratch ----------------
__device__ hf g_x1h[4096 * 1024];
__device__ hf g_x2h[8192 * 768];
__device__ hf g_w1h[3][1024 * 1024];   // transposed [N][K]
__device__ hf g_w2h[3][1024 * 768];

__device__ hf g_q1h[BB * SS1 * HD];
__device__ hf g_k1h[BB * SS1 * HD];
__device__ hf g_v1h[BB * SS1 * HD];
__device__ hf g_v1th[BB * HH * DD * SS1];
__device__ hf g_q2h[BB * SS2 * HD];
__device__ hf g_k2h[BB * SS2 * HD];
__device__ hf g_v2h[BB * SS2 * HD];
__device__ hf g_v2th[BB * HH * DD * SS2];

// ---------------- helpers ----------------
__device__ __forceinline__ uint32_t smem_u32(const void* p) {
    uint32_t a;
    asm("{ .reg .u64 t; cvta.to.shared.u64 t, %1; cvt.u32.u64 %0, t; }"
        : "=r"(a) : "l"(p));
    return a;
}
__device__ __forceinline__ void cp16(uint32_t dst, const void* src) {
    asm volatile("cp.async.cg.shared.global [%0], [%1], 16;\n" :: "r"(dst), "l"(src));
}
__device__ __forceinline__ void ldsm_x4(uint32_t& r0, uint32_t& r1,
                                        uint32_t& r2, uint32_t& r3, uint32_t a) {
    asm volatile("ldmatrix.sync.aligned.m8n8.x4.shared.b16 {%0,%1,%2,%3}, [%4];"
                 : "=r"(r0), "=r"(r1), "=r"(r2), "=r"(r3) : "r"(a));
}
__device__ __forceinline__ void mma16816(float* c, uint32_t a0, uint32_t a1,
                                         uint32_t a2, uint32_t a3,
                                         uint32_t b0, uint32_t b1) {
    asm volatile(
        "mma.sync.aligned.m16n8k16.row.col.f32.f16.f16.f32 "
        "{%0,%1,%2,%3}, {%4,%5,%6,%7}, {%8,%9}, {%0,%1,%2,%3};"
        : "+f"(c[0]), "+f"(c[1]), "+f"(c[2]), "+f"(c[3])
        : "r"(a0), "r"(a1), "r"(a2), "r"(a3), "r"(b0), "r"(b1));
}
__device__ __forceinline__ uint32_t packhf(hf a, hf b) {
    __half2 t = __halves2half2(a, b);
    return *reinterpret_cast<uint32_t*>(&t);
}

// ---------------- convert kernels ----------------
__global__ void xcvt(const float4* __restrict__ x, uint2* __restrict__ h, int n4) {
    int i = blockIdx.x * blockDim.x + threadIdx.x;
    if (i >= n4) return;
    float4 v = x[i];
    uint2 hp;
    hp.x = packhf(__float2half(v.x), __float2half(v.y));
    hp.y = packhf(__float2half(v.z), __float2half(v.w));
    h[i] = hp;
}

struct WS {
    const float* W[6];
    hf* Wh[6];
    int K[6];
};

__global__ void wsplit_all(WS ws) {
    const int z = blockIdx.z;
    const int K = ws.K[z];
    const int N = 1024;
    const int k0 = blockIdx.y * 32, n0 = blockIdx.x * 32;
    if (k0 >= K) return;
    __shared__ float t[32][33];
    const float* W = ws.W[z];
    hf* Wh = ws.Wh[z];
    int tx = threadIdx.x, ty = threadIdx.y;
#pragma unroll
    for (int i = 0; i < 4; i++)
        t[ty + i * 8][tx] = W[(size_t)(k0 + ty + i * 8) * N + n0 + tx];
    __syncthreads();
#pragma unroll
    for (int i = 0; i < 4; i++) {
        float v = t[tx][ty + i * 8];
        size_t o = (size_t)(n0 + ty + i * 8) * K + k0 + tx;
        Wh[o] = __float2half(v);
    }
}

struct VTP {
    const hf* V[2];
    hf* Vt[2];
    int S[2];
};

__global__ void vtrans_all(VTP p) {
    const int part = blockIdx.z >> 7;
    const int bh = blockIdx.z & 127, b = bh >> 3, h = bh & 7;
    const int S = p.S[part];
    const int s0 = blockIdx.y * 32;
    if (s0 >= S) return;
    const int d0 = blockIdx.x * 32;
    __shared__ float t[32][33];
    const hf* V = p.V[part];
    hf* Vt = p.Vt[part];
    const int tx = threadIdx.x, ty = threadIdx.y;
#pragma unroll
    for (int i = 0; i < 4; i++)
        t[ty + i * 8][tx] = __half2float(
            V[(size_t)(b * S + s0 + ty + i * 8) * HD + h * DD + d0 + tx]);
    __syncthreads();
#pragma unroll
    for (int i = 0; i < 4; i++) {
        size_t o = ((size_t)bh * DD + d0 + ty + i * 8) * S + s0 + tx;
        Vt[o] = __float2half(t[tx][ty + i * 8]);
    }
}

// ===========================================================================
// 4-stage pipelined mainloop (QKV GEMM only)
// ===========================================================================

#define MAINLOOP(LOADBODY)                                                     \
    for (int s = 0; s < NSTAGE - 1; ++s) {                                     \
        if (s < C) { const int c_ = s; const int stg_ = s; LOADBODY }          \
        asm volatile("cp.async.commit_group;\n");                              \
    }                                                                          \
    for (int c = 0; c < C; ++c) {                                              \
        asm volatile("cp.async.wait_group %0;\n" :: "n"(NSTAGE - 2));          \
        __syncthreads();                                                       \
        const int buf = c & (NSTAGE - 1);                                      \
        const uint32_t sa = asb + buf * TILEB + a_lm;                          \
        const uint32_t sb2 = bsb + buf * TILEB + b_lm;                         \
        _Pragma("unroll")                                                      \
        for (int kk = 0; kk < 2; kk++) {                                       \
            uint32_t a[4][4], bbf[2][4];                                       \
            _Pragma("unroll")                                                  \
            for (int i = 0; i < 4; i++)                                        \
                ldsm_x4(a[i][0], a[i][1], a[i][2], a[i][3],                    \
                        sa + i * 16 * (PADK * 2) + kk * 32);                   \
            _Pragma("unroll")                                                  \
            for (int j2 = 0; j2 < 2; j2++)                                     \
                ldsm_x4(bbf[j2][0], bbf[j2][1], bbf[j2][2], bbf[j2][3],        \
                        sb2 + j2 * 16 * (PADK * 2) + kk * 32);                 \
            _Pragma("unroll")                                                  \
            for (int i = 0; i < 4; i++)                                        \
                _Pragma("unroll")                                              \
                for (int j = 0; j < 4; j++) {                                  \
                    int j2 = j >> 1, jo = j & 1;                               \
                    mma16816(acc[i][j], a[i][0], a[i][1], a[i][2], a[i][3],    \
                             bbf[j2][jo], bbf[j2][jo + 2]);                    \
                }                                                              \
        }                                                                      \
        if (c + NSTAGE - 1 < C) {                                              \
            const int c_ = c + NSTAGE - 1;                                     \
            const int stg_ = c_ & (NSTAGE - 1);                                \
            LOADBODY                                                           \
        }                                                                      \
        asm volatile("cp.async.commit_group;\n");                              \
    }

// ---------------------------------------------------------------------------
// QKV HMMA GEMM (unchanged from R13): both streams, one launch, fp16 epilogue
// ---------------------------------------------------------------------------
struct G6 {
    const hf* A[6];
    const hf* Wh[6];
    const float* bias[6];
    hf* out[6];
    int K[6];
    int M[6];
};

__global__ __launch_bounds__(256) void hmma_qkv_all(G6 g) {
    const int N = 1024;
    extern __shared__ __align__(128) char smem[];
    const uint32_t asb = smem_u32(smem);
    const uint32_t bsb = asb + NSTAGE * TILEB;

    const int z = blockIdx.z;
    const int bm = blockIdx.y * 128;
    if (bm >= g.M[z]) return;
    const int bn = blockIdx.x * 128;
    const int K = g.K[z];
    const int C = K / 32;

    const int tid = threadIdx.x;
    const int wid = tid >> 5, lane = tid & 31;
    const int wm = wid >> 2, wn = wid & 3;
    const hf* Ah = g.A[z];
    const hf* Wh = g.Wh[z];

    float acc[4][4][4];
#pragma unroll
    for (int i = 0; i < 4; i++)
#pragma unroll
        for (int j = 0; j < 4; j++)
#pragma unroll
            for (int r = 0; r < 4; r++) acc[i][j][r] = 0.f;

    const int r0 = tid >> 2, s0 = (tid & 3);
    const uint32_t a_lm = (uint32_t)((wm * 64 + (lane & 15)) * (PADK * 2) + (lane >> 4) * 16);
    const uint32_t b_lm = (uint32_t)((wn * 32 + (lane & 15)) * (PADK * 2) + (lane >> 4) * 16);

#define QKV_LOAD {                                                             \
        const int kc = c_;                                                     \
        const char* ab = (const char*)(Ah + (size_t)bm * K + kc * 32);         \
        const char* bb = (const char*)(Wh + (size_t)bn * K + kc * 32);         \
        const size_t rs = (size_t)K * 2;                                       \
        const uint32_t sa_ = asb + stg_ * TILEB;                               \
        const uint32_t sb_ = bsb + stg_ * TILEB;                               \
        _Pragma("unroll")                                                      \
        for (int u = 0; u < 2; u++) {                                          \
            int row = r0 + u * 64;                                             \
            uint32_t off = (uint32_t)(row * (PADK * 2) + s0 * 16);             \
            cp16(sa_ + off, ab + (size_t)row * rs + s0 * 16);                  \
            cp16(sb_ + off, bb + (size_t)row * rs + s0 * 16);                  \
        }                                                                      \
    }

    MAINLOOP(QKV_LOAD)

    hf* outp = g.out[z];
    const float* bias = g.bias[z];
#pragma unroll
    for (int i = 0; i < 4; i++) {
#pragma unroll
        for (int j = 0; j < 4; j++) {
            int m = bm + wm * 64 + i * 16 + (lane >> 2);
            int n = bn + wn * 32 + j * 8 + (lane & 3) * 2;
            float b0 = __ldg(bias + n), b1 = __ldg(bias + n + 1);
            *reinterpret_cast<uint32_t*>(outp + (size_t)m * N + n) =
                packhf(__float2half(acc[i][j][0] + b0), __float2half(acc[i][j][1] + b1));
            *reinterpret_cast<uint32_t*>(outp + (size_t)(m + 8) * N + n) =
                packhf(__float2half(acc[i][j][2] + b0), __float2half(acc[i][j][3] + b1));
        }
    }
}

// ---------------------------------------------------------------------------
// Fused attention: one block = (part, bh, 32 q-rows).
//   Phase 1: scores = Q@K^T (full row span in regs), warp tile 16 x 128.
//   Phase 2: softmax in regs (quad shfl + smem cross-warp reduce) -> P smem fp16.
//   Phase 3: O = P@V, V streamed from Vt [D,S], warp tile 16 x 32(D).
// ---------------------------------------------------------------------------
struct FAP {
    const hf* Qh[2];
    const hf* Kh[2];
    const hf* Vth[2];
    const float* mask[2];
    float* O[2];
    int Sq[2], Sk[2];
};

__global__ __launch_bounds__(256) void fused_attn(FAP p, float scale) {
    extern __shared__ __align__(128) char smem[];
    const uint32_t sb = smem_u32(smem);
    const uint32_t ring = sb + FA_RING;
    const uint32_t qb = sb + FA_Q;
    const uint32_t pb = sb + FA_P;
    float* red = (float*)(smem + FA_RED);
    float* msk = (float*)(smem + FA_MASK);

    const int part = blockIdx.z >> 7;
    const int bh = blockIdx.z & 127, b = bh >> 3, h = bh & 7;
    const int Sq = p.Sq[part], Sk = p.Sk[part];
    const int qm0 = blockIdx.y * 32;
    if (qm0 >= Sq) return;

    const int tid = threadIdx.x;
    const int wid = tid >> 5, lane = tid & 31;
    const int wm = wid >> 2, wn = wid & 3;   // wm: 2 groups of 16 rows; wn: 4 col slices

    const hf* Qh = p.Qh[part];
    const hf* Kh = p.Kh[part];
    const hf* Vth = p.Vth[part];
    const int nct = Sk >> 7;          // 2 or 4 column chunks of 128
    const int CT = nct * 4;           // scores pipeline iters (4 k-chunks each)
    const int PSTR = (Sk + 8) * 2;    // P smem row stride (bytes)

    // mask row -> smem (plain loads; ordered by later barriers)
    for (int i = tid; i < Sk; i += 256)
        msk[i] = __ldg(p.mask[part] + b * Sk + i);

    // ---------- phase 1: scores ----------
    float acc[4][4][4];
#pragma unroll
    for (int i = 0; i < 4; i++)
#pragma unroll
        for (int j = 0; j < 4; j++)
#pragma unroll
            for (int r = 0; r < 4; r++) acc[i][j][r] = 0.f;

#define FA_KLOAD(t_, s_) {                                                     \
        const int nc = (t_) >> 2, kc = (t_) & 3;                               \
        const char* kg = (const char*)(Kh +                                    \
            (size_t)(b * Sk + nc * 128) * HD + h * DD + kc * 32);              \
        const uint32_t st = ring + (s_) * TILEB;                               \
        _Pragma("unroll")                                                      \
        for (int u = 0; u < 2; u++) {                                          \
            int seg = tid + u * 256;                                           \
            int row = seg >> 2, sq = seg & 3;                                  \
            cp16(st + row * 80 + sq * 16, kg + (size_t)row * (HD * 2) + sq * 16); \
        }                                                                      \
    }

    // prologue: Q tile (32x128, stride 272B) + first ring stage share group 0
    {
        const char* qg = (const char*)(Qh + (size_t)(b * Sq + qm0) * HD + h * DD);
#pragma unroll
        for (int u = 0; u < 2; u++) {
            int seg = tid + u * 256;
            int row = seg >> 4, cb = (seg & 15) * 16;
            cp16(qb + row * 272 + cb, qg + (size_t)row * (HD * 2) + cb);
        }
    }
    for (int s = 0; s < 3; ++s) {
        if (s < CT) FA_KLOAD(s, s)
        asm volatile("cp.async.commit_group;\n");
    }

    for (int t = 0; t < CT; ++t) {
        asm volatile("cp.async.wait_group 2;\n");
        __syncthreads();
        const int nc = t >> 2, kc = t & 3;
        const uint32_t abase = qb + (wm * 16 + (lane & 15)) * 272
                             + kc * 64 + (lane >> 4) * 16;
        const uint32_t bbase = ring + (t & 3) * TILEB
                             + (wn * 32 + (lane & 15)) * 80 + (lane >> 4) * 16;
#pragma unroll
        for (int kk = 0; kk < 2; kk++) {
            uint32_t a0, a1, a2, a3, bbf[2][4];
            ldsm_x4(a0, a1, a2, a3, abase + kk * 32);
#pragma unroll
            for (int j2 = 0; j2 < 2; j2++)
                ldsm_x4(bbf[j2][0], bbf[j2][1], bbf[j2][2], bbf[j2][3],
                        bbase + j2 * 16 * 80 + kk * 32);
#pragma unroll
            for (int j = 0; j < 4; j++) {
                int j2 = j >> 1, jo = j & 1;
                mma16816(acc[nc][j], a0, a1, a2, a3, bbf[j2][jo], bbf[j2][jo + 2]);
            }
        }
        if (t + 3 < CT) FA_KLOAD(t + 3, (t + 3) & 3)
        asm volatile("cp.async.commit_group;\n");
    }
    asm volatile("cp.async.wait_group 0;\n");
    __syncthreads();

    // ---------- phase 2: softmax ----------
    const int rA = wm * 16 + (lane >> 2);
    const int rB = rA + 8;
    float mxA = -INFINITY, mxB = -INFINITY;
    for (int nc = 0; nc < nct; nc++)
#pragma unroll
        for (int j = 0; j < 4; j++) {
            int col = nc * 128 + wn * 32 + j * 8 + (lane & 3) * 2;
            float m0 = msk[col], m1 = msk[col + 1];
            acc[nc][j][0] = acc[nc][j][0] * scale + m0;
            acc[nc][j][1] = acc[nc][j][1] * scale + m1;
            acc[nc][j][2] = acc[nc][j][2] * scale + m0;
            acc[nc][j][3] = acc[nc][j][3] * scale + m1;
            mxA = fmaxf(mxA, fmaxf(acc[nc][j][0], acc[nc][j][1]));
            mxB = fmaxf(mxB, fmaxf(acc[nc][j][2], acc[nc][j][3]));
        }
    mxA = fmaxf(mxA, __shfl_xor_sync(0xffffffffu, mxA, 1));
    mxA = fmaxf(mxA, __shfl_xor_sync(0xffffffffu, mxA, 2));
    mxB = fmaxf(mxB, __shfl_xor_sync(0xffffffffu, mxB, 1));
    mxB = fmaxf(mxB, __shfl_xor_sync(0xffffffffu, mxB, 2));
    if ((lane & 3) == 0) { red[rA * 4 + wn] = mxA; red[rB * 4 + wn] = mxB; }
    __syncthreads();
    mxA = fmaxf(fmaxf(red[rA * 4 + 0], red[rA * 4 + 1]),
                fmaxf(red[rA * 4 + 2], red[rA * 4 + 3]));
    mxB = fmaxf(fmaxf(red[rB * 4 + 0], red[rB * 4 + 1]),
                fmaxf(red[rB * 4 + 2], red[rB * 4 + 3]));
    __syncthreads();

    float sA = 0.f, sB = 0.f;
    for (int nc = 0; nc < nct; nc++)
#pragma unroll
        for (int j = 0; j < 4; j++) {
            float e0 = __expf(acc[nc][j][0] - mxA);
            float e1 = __expf(acc[nc][j][1] - mxA);
            float e2 = __expf(acc[nc][j][2] - mxB);
            float e3 = __expf(acc[nc][j][3] - mxB);
            acc[nc][j][0] = e0; acc[nc][j][1] = e1;
            acc[nc][j][2] = e2; acc[nc][j][3] = e3;
            sA += e0 + e1; sB += e2 + e3;
        }
    sA += __shfl_xor_sync(0xffffffffu, sA, 1);
    sA += __shfl_xor_sync(0xffffffffu, sA, 2);
    sB += __shfl_xor_sync(0xffffffffu, sB, 1);
    sB += __shfl_xor_sync(0xffffffffu, sB, 2);
    if ((lane & 3) == 0) { red[rA * 4 + wn] = sA; red[rB * 4 + wn] = sB; }
    __syncthreads();
    float invA = 1.f / (red[rA * 4 + 0] + red[rA * 4 + 1] +
                        red[rA * 4 + 2] + red[rA * 4 + 3]);
    float invB = 1.f / (red[rB * 4 + 0] + red[rB * 4 + 1] +
                        red[rB * 4 + 2] + red[rB * 4 + 3]);

    // P -> smem fp16
    for (int nc = 0; nc < nct; nc++)
#pragma unroll
        for (int j = 0; j < 4; j++) {
            int col = nc * 128 + wn * 32 + j * 8 + (lane & 3) * 2;
            *(uint32_t*)(smem + FA_P + rA * PSTR + col * 2) =
                packhf(__float2half(acc[nc][j][0] * invA),
                       __float2half(acc[nc][j][1] * invA));
            *(uint32_t*)(smem + FA_P + rB * PSTR + col * 2) =
                packhf(__float2half(acc[nc][j][2] * invB),
                       __float2half(acc[nc][j][3] * invB));
        }
    __syncthreads();

    // ---------- phase 3: O = P @ V ----------
    const int C2 = Sk >> 5;
    float o[4][4];
#pragma unroll
    for (int j = 0; j < 4; j++)
#pragma unroll
        for (int r = 0; r < 4; r++) o[j][r] = 0.f;

#define FA_VLOAD(t_, s_) {                                                     \
        const char* vg = (const char*)(Vth + (size_t)bh * DD * Sk + (t_) * 32); \
        const uint32_t st = ring + (s_) * TILEB;                               \
        _Pragma("unroll")                                                      \
        for (int u = 0; u < 2; u++) {                                          \
            int seg = tid + u * 256;                                           \
            int row = seg >> 2, sq = seg & 3;                                  \
            cp16(st + row * 80 + sq * 16, vg + (size_t)row * (Sk * 2) + sq * 16); \
        }                                                                      \
    }

    for (int s = 0; s < 3; ++s) {
        if (s < C2) FA_VLOAD(s, s)
        asm volatile("cp.async.commit_group;\n");
    }
    for (int t = 0; t < C2; ++t) {
        asm volatile("cp.async.wait_group 2;\n");
        __syncthreads();
        const uint32_t abase = pb + (wm * 16 + (lane & 15)) * PSTR
                             + t * 64 + (lane >> 4) * 16;
        const uint32_t bbase = ring + (t & 3) * TILEB
                             + (wn * 32 + (lane & 15)) * 80 + (lane >> 4) * 16;
#pragma unroll
        for (int kk = 0; kk < 2; kk++) {
            uint32_t a0, a1, a2, a3, bbf[2][4];
            ldsm_x4(a0, a1, a2, a3, abase + kk * 32);
#pragma unroll
            for (int j2 = 0; j2 < 2; j2++)
                ldsm_x4(bbf[j2][0], bbf[j2][1], bbf[j2][2], bbf[j2][3],
                        bbase + j2 * 16 * 80 + kk * 32);
#pragma unroll
            for (int j = 0; j < 4; j++) {
                int j2 = j >> 1, jo = j & 1;
                mma16816(o[j], a0, a1, a2, a3, bbf[j2][jo], bbf[j2][jo + 2]);
            }
        }
        if (t + 3 < C2) FA_VLOAD(t + 3, (t + 3) & 3)
        asm volatile("cp.async.commit_group;\n");
    }

    // epilogue -> O[b, m, h, d] fp32
    float* O = p.O[part];
    const int m = qm0 + wm * 16 + (lane >> 2);
#pragma unroll
    for (int j = 0; j < 4; j++) {
        int d = wn * 32 + j * 8 + (lane & 3) * 2;
        float2 v0 = make_float2(o[j][0], o[j][1]);
        float2 v1 = make_float2(o[j][2], o[j][3]);
        *reinterpret_cast<float2*>(
            O + ((size_t)(b * Sq + m) * HH + h) * DD + d) = v0;
        *reinterpret_cast<float2*>(
            O + ((size_t)(b * Sq + m + 8) * HH + h) * DD + d) = v1;
    }
}

// ---------------------------------------------------------------------------
extern "C" void kernel_launch(void* const* d_in, const int* in_sizes, int n_in,
                              void* d_out, int out_size) {
    const float* x1    = (const float*)d_in[0];
    const float* mask1 = (const float*)d_in[1];
    const float* x2    = (const float*)d_in[2];
    const float* mask2 = (const float*)d_in[3];
    const float* W1[3] = {(const float*)d_in[4], (const float*)d_in[6], (const float*)d_in[8]};
    const float* b1[3] = {(const float*)d_in[5], (const float*)d_in[7], (const float*)d_in[9]};
    const float* W2[3] = {(const float*)d_in[10], (const float*)d_in[12], (const float*)d_in[14]};
    const float* b2[3] = {(const float*)d_in[11], (const float*)d_in[13], (const float*)d_in[15]};
    float* out = (float*)d_out;

    hf *x1h, *x2h, *w1h, *w2h;
    cudaGetSymbolAddress((void**)&x1h, g_x1h);
    cudaGetSymbolAddress((void**)&x2h, g_x2h);
    cudaGetSymbolAddress((void**)&w1h, g_w1h);
    cudaGetSymbolAddress((void**)&w2h, g_w2h);

    hf *q1h, *k1h, *v1h, *v1th, *q2h, *k2h, *v2h, *v2th;
    cudaGetSymbolAddress((void**)&q1h, g_q1h);
    cudaGetSymbolAddress((void**)&k1h, g_k1h);
    cudaGetSymbolAddress((void**)&v1h, g_v1h);
    cudaGetSymbolAddress((void**)&v1th, g_v1th);
    cudaGetSymbolAddress((void**)&q2h, g_q2h);
    cudaGetSymbolAddress((void**)&k2h, g_k2h);
    cudaGetSymbolAddress((void**)&v2h, g_v2h);
    cudaGetSymbolAddress((void**)&v2th, g_v2th);

    cudaFuncSetAttribute(hmma_qkv_all, cudaFuncAttributeMaxDynamicSharedMemorySize, SMEM_DYN);
    cudaFuncSetAttribute(fused_attn, cudaFuncAttributeMaxDynamicSharedMemorySize, FA_SMEM);

    const float scale = 1.0f / sqrtf((float)DD);
    dim3 blk(256);

    // 1-2: input converts
    {
        int n4 = 4096 * 1024 / 4;
        xcvt<<<n4 / 256, 256>>>((const float4*)x1, (uint2*)x1h, n4);
    }
    {
        int n4 = 8192 * 768 / 4;
        xcvt<<<n4 / 256, 256>>>((const float4*)x2, (uint2*)x2h, n4);
    }
    // 3: weight converts (transposed)
    {
        WS ws;
        for (int i = 0; i < 3; i++) {
            ws.W[i] = W1[i];
            ws.Wh[i] = w1h + (size_t)i * 1024 * 1024;
            ws.K[i] = 1024;
            ws.W[3 + i] = W2[i];
            ws.Wh[3 + i] = w2h + (size_t)i * 1024 * 768;
            ws.K[3 + i] = 768;
        }
        wsplit_all<<<dim3(32, 32, 6), dim3(32, 8)>>>(ws);
    }

    // 4: all 6 QKV GEMMs, one launch, fp16 epilogue
    {
        G6 g;
        for (int i = 0; i < 3; i++) {
            g.A[i] = x1h;
            g.Wh[i] = w1h + (size_t)i * 1024 * 1024;
            g.bias[i] = b1[i];
            g.K[i] = 1024;
            g.M[i] = BB * SS1;
            g.A[3 + i] = x2h;
            g.Wh[3 + i] = w2h + (size_t)i * 1024 * 768;
            g.bias[3 + i] = b2[i];
            g.K[3 + i] = 768;
            g.M[3 + i] = BB * SS2;
        }
        g.out[0] = q1h; g.out[1] = k1h; g.out[2] = v1h;
        g.out[3] = q2h; g.out[4] = k2h; g.out[5] = v2h;
        hmma_qkv_all<<<dim3(8, 64, 6), blk, SMEM_DYN>>>(g);
    }

    // 5: merged V transposes
    {
        VTP p;
        p.V[0] = v1h; p.Vt[0] = v1th; p.S[0] = SS1;
        p.V[1] = v2h; p.Vt[1] = v2th; p.S[1] = SS2;
        vtrans_all<<<dim3(4, 16, 256), dim3(32, 8)>>>(p);
    }

    // 6: fused attention (both directions)
    {
        FAP p;
        p.Qh[0] = q2h; p.Kh[0] = k1h; p.Vth[0] = v1th;
        p.mask[0] = mask1; p.O[0] = out;
        p.Sq[0] = SS2; p.Sk[0] = SS1;
        p.Qh[1] = q1h; p.Kh[1] = k2h; p.Vth[1] = v2th;
        p.mask[1] = mask2; p.O[1] = out + C1_ELEMS;
        p.Sq[1] = SS1; p.Sk[1] = SS2;
        fused_attn<<<dim3(1, 16, 256), blk, FA_SMEM>>>(p, scale);
    }
}

// round 15
// speedup vs baseline: 1.1508x; 1.1508x over previous
#include <cuda_runtime.h>
#include <cuda_fp16.h>
#include <cstdint>
#include <math.h>

// ===========================================================================
// BertBiAttention on GB300 (sm_103 ptxas target -> mma.sync HMMA everywhere)
//   B=16, S1=256, S2=512, V_HID=1024, T_HID=768, BI_HID=1024, H=8, D=128
// Round 15: R13 structure (best known) + Q-resident multi-chunk scores kernel
//   (Q tile loaded once, K ring streams continuously across n-chunks, per-
//   chunk epilogue from skeleton-identical fragments). xcvt launches merged.
// ===========================================================================

#define BB   16
#define SS1  256
#define SS2  512
#define HH   8
#define DD   128
#define HD   1024
#define C1_ELEMS ((size_t)BB * SS2 * HD)

typedef __half hf;

#define PADK 40
#define NSTAGE 4
#define TILEB (128 * PADK * 2)          // 10240 bytes per tile
#define SMEM_DYN (2 * NSTAGE * TILEB)   // 81920 bytes

// ---------------- scratch ----------------
__device__ hf g_x1h[4096 * 1024];
__device__ hf g_x2h[8192 * 768];
__device__ hf g_w1h[3][1024 * 1024];   // transposed [N][K]
__device__ hf g_w2h[3][1024 * 768];

__device__ hf g_q1h[BB * SS1 * HD];
__device__ hf g_k1h[BB * SS1 * HD];
__device__ hf g_v1h[BB * SS1 * HD];
__device__ hf g_v1th[BB * HH * DD * SS1];
__device__ hf g_q2h[BB * SS2 * HD];
__device__ hf g_k2h[BB * SS2 * HD];
__device__ hf g_v2h[BB * SS2 * HD];
__device__ hf g_v2th[BB * HH * DD * SS2];

#define P_ELEMS ((size_t)BB * HH * SS2 * SS1)
__device__ float g_p1[P_ELEMS];
__device__ float g_p2[P_ELEMS];
__device__ hf g_p1h[P_ELEMS];
__device__ hf g_p2h[P_ELEMS];

// ---------------- helpers ----------------
__device__ __forceinline__ uint32_t smem_u32(const void* p) {
    uint32_t a;
    asm("{ .reg .u64 t; cvta.to.shared.u64 t, %1; cvt.u32.u64 %0, t; }"
        : "=r"(a) : "l"(p));
    return a;
}
__device__ __forceinline__ void cp16(uint32_t dst, const void* src) {
    asm volatile("cp.async.cg.shared.global [%0], [%1], 16;\n" :: "r"(dst), "l"(src));
}
__device__ __forceinline__ void ldsm_x4(uint32_t& r0, uint32_t& r1,
                                        uint32_t& r2, uint32_t& r3, uint32_t a) {
    asm volatile("ldmatrix.sync.aligned.m8n8.x4.shared.b16 {%0,%1,%2,%3}, [%4];"
                 : "=r"(r0), "=r"(r1), "=r"(r2), "=r"(r3) : "r"(a));
}
__device__ __forceinline__ void mma16816(float* c, uint32_t a0, uint32_t a1,
                                         uint32_t a2, uint32_t a3,
                                         uint32_t b0, uint32_t b1) {
    asm volatile(
        "mma.sync.aligned.m16n8k16.row.col.f32.f16.f16.f32 "
        "{%0,%1,%2,%3}, {%4,%5,%6,%7}, {%8,%9}, {%0,%1,%2,%3};"
        : "+f"(c[0]), "+f"(c[1]), "+f"(c[2]), "+f"(c[3])
        : "r"(a0), "r"(a1), "r"(a2), "r"(a3), "r"(b0), "r"(b1));
}
__device__ __forceinline__ uint32_t packhf(hf a, hf b) {
    __half2 t = __halves2half2(a, b);
    return *reinterpret_cast<uint32_t*>(&t);
}

// ---------------- convert kernels ----------------
struct X2 {
    const float4* x[2];
    uint2* h[2];
    int n4[2];
};

__global__ void xcvt_all(X2 p) {
    const int part = blockIdx.y;
    int i = blockIdx.x * blockDim.x + threadIdx.x;
    if (i >= p.n4[part]) return;
    float4 v = p.x[part][i];
    uint2 hp;
    hp.x = packhf(__float2half(v.x), __float2half(v.y));
    hp.y = packhf(__float2half(v.z), __float2half(v.w));
    p.h[part][i] = hp;
}

struct WS {
    const float* W[6];
    hf* Wh[6];
    int K[6];
};

__global__ void wsplit_all(WS ws) {
    const int z = blockIdx.z;
    const int K = ws.K[z];
    const int N = 1024;
    const int k0 = blockIdx.y * 32, n0 = blockIdx.x * 32;
    if (k0 >= K) return;
    __shared__ float t[32][33];
    const float* W = ws.W[z];
    hf* Wh = ws.Wh[z];
    int tx = threadIdx.x, ty = threadIdx.y;
#pragma unroll
    for (int i = 0; i < 4; i++)
        t[ty + i * 8][tx] = W[(size_t)(k0 + ty + i * 8) * N + n0 + tx];
    __syncthreads();
#pragma unroll
    for (int i = 0; i < 4; i++) {
        float v = t[tx][ty + i * 8];
        size_t o = (size_t)(n0 + ty + i * 8) * K + k0 + tx;
        Wh[o] = __float2half(v);
    }
}

struct VTP {
    const hf* V[2];
    hf* Vt[2];
    int S[2];
};

__global__ void vtrans_all(VTP p) {
    const int part = blockIdx.z >> 7;
    const int bh = blockIdx.z & 127, b = bh >> 3, h = bh & 7;
    const int S = p.S[part];
    const int s0 = blockIdx.y * 32;
    if (s0 >= S) return;
    const int d0 = blockIdx.x * 32;
    __shared__ float t[32][33];
    const hf* V = p.V[part];
    hf* Vt = p.Vt[part];
    const int tx = threadIdx.x, ty = threadIdx.y;
#pragma unroll
    for (int i = 0; i < 4; i++)
        t[ty + i * 8][tx] = __half2float(
            V[(size_t)(b * S + s0 + ty + i * 8) * HD + h * DD + d0 + tx]);
    __syncthreads();
#pragma unroll
    for (int i = 0; i < 4; i++) {
        size_t o = ((size_t)bh * DD + d0 + ty + i * 8) * S + s0 + tx;
        Vt[o] = __float2half(t[tx][ty + i * 8]);
    }
}

// ===========================================================================
// 4-stage pipelined mainloop (QKV / ctx)
// ===========================================================================

#define MAINLOOP(LOADBODY)                                                     \
    for (int s = 0; s < NSTAGE - 1; ++s) {                                     \
        if (s < C) { const int c_ = s; const int stg_ = s; LOADBODY }          \
        asm volatile("cp.async.commit_group;\n");                              \
    }                                                                          \
    for (int c = 0; c < C; ++c) {                                              \
        asm volatile("cp.async.wait_group %0;\n" :: "n"(NSTAGE - 2));          \
        __syncthreads();                                                       \
        const int buf = c & (NSTAGE - 1);                                      \
        const uint32_t sa = asb + buf * TILEB + a_lm;                          \
        const uint32_t sb2 = bsb + buf * TILEB + b_lm;                         \
        _Pragma("unroll")                                                      \
        for (int kk = 0; kk < 2; kk++) {                                       \
            uint32_t a[4][4], bbf[2][4];                                       \
            _Pragma("unroll")                                                  \
            for (int i = 0; i < 4; i++)                                        \
                ldsm_x4(a[i][0], a[i][1], a[i][2], a[i][3],                    \
                        sa + i * 16 * (PADK * 2) + kk * 32);                   \
            _Pragma("unroll")                                                  \
            for (int j2 = 0; j2 < 2; j2++)                                     \
                ldsm_x4(bbf[j2][0], bbf[j2][1], bbf[j2][2], bbf[j2][3],        \
                        sb2 + j2 * 16 * (PADK * 2) + kk * 32);                 \
            _Pragma("unroll")                                                  \
            for (int i = 0; i < 4; i++)                                        \
                _Pragma("unroll")                                              \
                for (int j = 0; j < 4; j++) {                                  \
                    int j2 = j >> 1, jo = j & 1;                               \
                    mma16816(acc[i][j], a[i][0], a[i][1], a[i][2], a[i][3],    \
                             bbf[j2][jo], bbf[j2][jo + 2]);                    \
                }                                                              \
        }                                                                      \
        if (c + NSTAGE - 1 < C) {                                              \
            const int c_ = c + NSTAGE - 1;                                     \
            const int stg_ = c_ & (NSTAGE - 1);                                \
            LOADBODY                                                           \
        }                                                                      \
        asm volatile("cp.async.commit_group;\n");                              \
    }

// ---------------------------------------------------------------------------
// QKV HMMA GEMM (unchanged from R13)
// ---------------------------------------------------------------------------
struct G6 {
    const hf* A[6];
    const hf* Wh[6];
    const float* bias[6];
    hf* out[6];
    int K[6];
    int M[6];
};

__global__ __launch_bounds__(256) void hmma_qkv_all(G6 g) {
    const int N = 1024;
    extern __shared__ __align__(128) char smem[];
    const uint32_t asb = smem_u32(smem);
    const uint32_t bsb = asb + NSTAGE * TILEB;

    const int z = blockIdx.z;
    const int bm = blockIdx.y * 128;
    if (bm >= g.M[z]) return;
    const int bn = blockIdx.x * 128;
    const int K = g.K[z];
    const int C = K / 32;

    const int tid = threadIdx.x;
    const int wid = tid >> 5, lane = tid & 31;
    const int wm = wid >> 2, wn = wid & 3;
    const hf* Ah = g.A[z];
    const hf* Wh = g.Wh[z];

    float acc[4][4][4];
#pragma unroll
    for (int i = 0; i < 4; i++)
#pragma unroll
        for (int j = 0; j < 4; j++)
#pragma unroll
            for (int r = 0; r < 4; r++) acc[i][j][r] = 0.f;

    const int r0 = tid >> 2, s0 = (tid & 3);
    const uint32_t a_lm = (uint32_t)((wm * 64 + (lane & 15)) * (PADK * 2) + (lane >> 4) * 16);
    const uint32_t b_lm = (uint32_t)((wn * 32 + (lane & 15)) * (PADK * 2) + (lane >> 4) * 16);

#define QKV_LOAD {                                                             \
        const int kc = c_;                                                     \
        const char* ab = (const char*)(Ah + (size_t)bm * K + kc * 32);         \
        const char* bb = (const char*)(Wh + (size_t)bn * K + kc * 32);         \
        const size_t rs = (size_t)K * 2;                                       \
        const uint32_t sa_ = asb + stg_ * TILEB;                               \
        const uint32_t sb_ = bsb + stg_ * TILEB;                               \
        _Pragma("unroll")                                                      \
        for (int u = 0; u < 2; u++) {                                          \
            int row = r0 + u * 64;                                             \
            uint32_t off = (uint32_t)(row * (PADK * 2) + s0 * 16);             \
            cp16(sa_ + off, ab + (size_t)row * rs + s0 * 16);                  \
            cp16(sb_ + off, bb + (size_t)row * rs + s0 * 16);                  \
        }                                                                      \
    }

    MAINLOOP(QKV_LOAD)

    hf* outp = g.out[z];
    const float* bias = g.bias[z];
#pragma unroll
    for (int i = 0; i < 4; i++) {
#pragma unroll
        for (int j = 0; j < 4; j++) {
            int m = bm + wm * 64 + i * 16 + (lane >> 2);
            int n = bn + wn * 32 + j * 8 + (lane & 3) * 2;
            float b0 = __ldg(bias + n), b1 = __ldg(bias + n + 1);
            *reinterpret_cast<uint32_t*>(outp + (size_t)m * N + n) =
                packhf(__float2half(acc[i][j][0] + b0), __float2half(acc[i][j][1] + b1));
            *reinterpret_cast<uint32_t*>(outp + (size_t)(m + 8) * N + n) =
                packhf(__float2half(acc[i][j][2] + b0), __float2half(acc[i][j][3] + b1));
        }
    }
}

// ---------------------------------------------------------------------------
// scores HMMA, Q-resident multi-chunk: one block = 128 q-rows x full Sk.
// Q tile (128x128) loaded once into 4 skeleton-format sub-tiles; K streamed
// through the 4-stage ring continuously; per-chunk epilogue (scale+mask).
// ---------------------------------------------------------------------------
struct SCP {
    const hf* Qh[2];
    const hf* Kh[2];
    const float* mask[2];
    float* Sout[2];
    int Sq[2], Sk[2];
};

__global__ __launch_bounds__(256) void hmma_scores_all(SCP p, float scale) {
    extern __shared__ __align__(128) char smem[];
    const uint32_t ring = smem_u32(smem);              // 4 * TILEB
    const uint32_t qb = ring + NSTAGE * TILEB;         // 4 * TILEB (Q sub-tiles)

    const int part = blockIdx.z >> 7;
    const int bh = blockIdx.z & 127, b = bh >> 3, h = bh & 7;
    const int Sq = p.Sq[part], Sk = p.Sk[part];
    const int bm = blockIdx.y * 128;
    if (bm >= Sq) return;
    const int NT = (Sk >> 7) * 4;    // 8 (Sk=256) or 16 (Sk=512)

    const int tid = threadIdx.x;
    const int wid = tid >> 5, lane = tid & 31;
    const int wm = wid >> 2, wn = wid & 3;
    const hf* Qh = p.Qh[part];
    const hf* Kh = p.Kh[part];
    float* Sout = p.Sout[part];
    const float* mask = p.mask[part];

    float acc[4][4];
#pragma unroll
    for (int j = 0; j < 4; j++)
#pragma unroll
        for (int r = 0; r < 4; r++) acc[j][r] = 0.f;
    float acc2[4][4];
#pragma unroll
    for (int j = 0; j < 4; j++)
#pragma unroll
        for (int r = 0; r < 4; r++) acc2[j][r] = 0.f;

    const uint32_t a_lm = (uint32_t)((wm * 64 + (lane & 15)) * 80 + (lane >> 4) * 16);
    const uint32_t b_lm = (uint32_t)((wn * 32 + (lane & 15)) * 80 + (lane >> 4) * 16);

#define SCK_LOAD(t_, s_) {                                                     \
        const int nc = (t_) >> 2, kc = (t_) & 3;                               \
        const char* kg = (const char*)(Kh +                                    \
            (size_t)(b * Sk + nc * 128) * HD + h * DD + kc * 32);              \
        const uint32_t st = ring + (s_) * TILEB;                               \
        _Pragma("unroll")                                                      \
        for (int u = 0; u < 2; u++) {                                          \
            int seg = tid + u * 256;                                           \
            int row = seg >> 2, sq = seg & 3;                                  \
            cp16(st + row * 80 + sq * 16,                                      \
                 kg + (size_t)row * (HD * 2) + sq * 16);                       \
        }                                                                      \
    }

    // prologue: Q tile (once) shares commit group with K stage 0
    {
        const char* qg = (const char*)(Qh + (size_t)(b * Sq + bm) * HD + h * DD);
#pragma unroll
        for (int u = 0; u < 8; u++) {
            int seg = tid + u * 256;          // 0..2047
            int kc = seg >> 9;
            int s2 = seg & 511;
            int row = s2 >> 2, sq = s2 & 3;
            cp16(qb + kc * TILEB + row * 80 + sq * 16,
                 qg + (size_t)row * (HD * 2) + kc * 64 + sq * 16);
        }
    }
    SCK_LOAD(0, 0)
    asm volatile("cp.async.commit_group;\n");
    SCK_LOAD(1, 1)
    asm volatile("cp.async.commit_group;\n");
    SCK_LOAD(2, 2)
    asm volatile("cp.async.commit_group;\n");

    for (int t = 0; t < NT; ++t) {
        asm volatile("cp.async.wait_group 2;\n");
        __syncthreads();
        const int kc = t & 3;
        const uint32_t sa = qb + kc * TILEB + a_lm;
        const uint32_t sb2 = ring + (t & 3) * TILEB + b_lm;
#pragma unroll
        for (int kk = 0; kk < 2; kk++) {
            uint32_t a[4][4], bbf[2][4];
#pragma unroll
            for (int i = 0; i < 4; i++)
                ldsm_x4(a[i][0], a[i][1], a[i][2], a[i][3],
                        sa + i * 16 * 80 + kk * 32);
#pragma unroll
            for (int j2 = 0; j2 < 2; j2++)
                ldsm_x4(bbf[j2][0], bbf[j2][1], bbf[j2][2], bbf[j2][3],
                        sb2 + j2 * 16 * 80 + kk * 32);
#pragma unroll
            for (int i = 0; i < 4; i++)
#pragma unroll
                for (int j = 0; j < 4; j++) {
                    int j2 = j >> 1, jo = j & 1;
                    float* ac = (i < 2) ? ((i == 0) ? acc[j] : acc[j]) : acc2[j];
                    // map: i in 0..3 rows frags; keep two halves in acc/acc2
                    (void)ac;
                }
            // explicit: frags i=0,1 -> acc rows (wm*64 + i*16), i=2,3 -> acc2
#pragma unroll
            for (int j = 0; j < 4; j++) {
                int j2 = j >> 1, jo = j & 1;
                mma16816(acc[j],  a[0][0], a[0][1], a[0][2], a[0][3],
                         bbf[j2][jo], bbf[j2][jo + 2]);
            }
#pragma unroll
            for (int j = 0; j < 4; j++) {
                int j2 = j >> 1, jo = j & 1;
                mma16816(acc2[j], a[1][0], a[1][1], a[1][2], a[1][3],
                         bbf[j2][jo], bbf[j2][jo + 2]);
            }
#pragma unroll
            for (int j = 0; j < 4; j++) {
                int j2 = j >> 1, jo = j & 1;
                mma16816(acc[j] + 0, a[2][0], a[2][1], a[2][2], a[2][3],
                         bbf[j2][jo], bbf[j2][jo + 2]);
            }
            // NOTE: the above triple block is wrong — replaced below.
        }
        // (compute rewritten below without the erroneous block)
        if (t + 3 < NT) SCK_LOAD(t + 3, (t + 3) & 3)
        asm volatile("cp.async.commit_group;\n");
        if ((t & 3) == 3) {
            const int nc = t >> 2;
            // epilogue handled after full-acc version below
            (void)nc;
        }
    }
    (void)Sout; (void)mask; (void)scale; (void)acc2;
}

// ---------------------------------------------------------------------------
// The multi-chunk scores kernel above had an authoring error mid-flight; the
// actual kernel used is this clean version with full 4x4 fragment arrays.
// ---------------------------------------------------------------------------
__global__ __launch_bounds__(256) void hmma_scores_mc(SCP p, float scale) {
    extern __shared__ __align__(128) char smem[];
    const uint32_t ring = smem_u32(smem);
    const uint32_t qb = ring + NSTAGE * TILEB;

    const int part = blockIdx.z >> 7;
    const int bh = blockIdx.z & 127, b = bh >> 3, h = bh & 7;
    const int Sq = p.Sq[part], Sk = p.Sk[part];
    const int bm = blockIdx.y * 128;
    if (bm >= Sq) return;
    const int NT = (Sk >> 7) * 4;

    const int tid = threadIdx.x;
    const int wid = tid >> 5, lane = tid & 31;
    const int wm = wid >> 2, wn = wid & 3;
    const hf* Qh = p.Qh[part];
    const hf* Kh = p.Kh[part];
    float* Sout = p.Sout[part];
    const float* mask = p.mask[part];

    float acc[4][4][4];
#pragma unroll
    for (int i = 0; i < 4; i++)
#pragma unroll
        for (int j = 0; j < 4; j++)
#pragma unroll
            for (int r = 0; r < 4; r++) acc[i][j][r] = 0.f;

    const uint32_t a_lm = (uint32_t)((wm * 64 + (lane & 15)) * 80 + (lane >> 4) * 16);
    const uint32_t b_lm = (uint32_t)((wn * 32 + (lane & 15)) * 80 + (lane >> 4) * 16);

    {
        const char* qg = (const char*)(Qh + (size_t)(b * Sq + bm) * HD + h * DD);
#pragma unroll
        for (int u = 0; u < 8; u++) {
            int seg = tid + u * 256;
            int kc = seg >> 9;
            int s2 = seg & 511;
            int row = s2 >> 2, sq = s2 & 3;
            cp16(qb + kc * TILEB + row * 80 + sq * 16,
                 qg + (size_t)row * (HD * 2) + kc * 64 + sq * 16);
        }
    }
    SCK_LOAD(0, 0)
    asm volatile("cp.async.commit_group;\n");
    SCK_LOAD(1, 1)
    asm volatile("cp.async.commit_group;\n");
    SCK_LOAD(2, 2)
    asm volatile("cp.async.commit_group;\n");

    for (int t = 0; t < NT; ++t) {
        asm volatile("cp.async.wait_group 2;\n");
        __syncthreads();
        const uint32_t sa = qb + (t & 3) * TILEB + a_lm;
        const uint32_t sb2 = ring + (t & 3) * TILEB + b_lm;
#pragma unroll
        for (int kk = 0; kk < 2; kk++) {
            uint32_t a[4][4], bbf[2][4];
#pragma unroll
            for (int i = 0; i < 4; i++)
                ldsm_x4(a[i][0], a[i][1], a[i][2], a[i][3],
                        sa + i * 16 * 80 + kk * 32);
#pragma unroll
            for (int j2 = 0; j2 < 2; j2++)
                ldsm_x4(bbf[j2][0], bbf[j2][1], bbf[j2][2], bbf[j2][3],
                        sb2 + j2 * 16 * 80 + kk * 32);
#pragma unroll
            for (int i = 0; i < 4; i++)
#pragma unroll
                for (int j = 0; j < 4; j++) {
                    int j2 = j >> 1, jo = j & 1;
                    mma16816(acc[i][j], a[i][0], a[i][1], a[i][2], a[i][3],
                             bbf[j2][jo], bbf[j2][jo + 2]);
                }
        }
        if (t + 3 < NT) SCK_LOAD(t + 3, (t + 3) & 3)
        asm volatile("cp.async.commit_group;\n");

        if ((t & 3) == 3) {
            const int nc = t >> 2;
            const int bn = nc * 128;
#pragma unroll
            for (int i = 0; i < 4; i++) {
#pragma unroll
                for (int j = 0; j < 4; j++) {
                    int m = bm + wm * 64 + i * 16 + (lane >> 2);
                    int n = bn + wn * 32 + j * 8 + (lane & 3) * 2;
                    float mk0 = __ldg(mask + b * Sk + n);
                    float mk1 = __ldg(mask + b * Sk + n + 1);
                    float2 v0 = make_float2(acc[i][j][0] * scale + mk0,
                                            acc[i][j][1] * scale + mk1);
                    float2 v1 = make_float2(acc[i][j][2] * scale + mk0,
                                            acc[i][j][3] * scale + mk1);
                    *reinterpret_cast<float2*>(Sout + ((size_t)bh * Sq + m) * Sk + n) = v0;
                    *reinterpret_cast<float2*>(Sout + ((size_t)bh * Sq + m + 8) * Sk + n) = v1;
                    acc[i][j][0] = 0.f; acc[i][j][1] = 0.f;
                    acc[i][j][2] = 0.f; acc[i][j][3] = 0.f;
                }
            }
        }
    }
}

// ---------------------------------------------------------------------------
// softmax -> fp16 P (unchanged from R13)
// ---------------------------------------------------------------------------
struct SMP {
    const float* S[2];
    hf* Ph[2];
    int rows0;
    int n[2];
};

__global__ __launch_bounds__(256) void softmax_all(SMP p, int rows_total) {
    int rg = (blockIdx.x * blockDim.x + threadIdx.x) >> 5;
    int lane = threadIdx.x & 31;
    if (rg >= rows_total) return;
    int part = (rg < p.rows0) ? 0 : 1;
    int row = (part == 0) ? rg : rg - p.rows0;
    const int n = p.n[part];
    const float2* r2 = reinterpret_cast<const float2*>(p.S[part] + (size_t)row * n);
    const int np = n >> 6;

    float v[16];
    float mx = -INFINITY;
#pragma unroll
    for (int c = 0; c < 8; c++) {
        if (c >= np) break;
        float2 t = r2[lane + c * 32];
        v[2 * c] = t.x; v[2 * c + 1] = t.y;
        mx = fmaxf(mx, fmaxf(t.x, t.y));
    }
#pragma unroll
    for (int o = 16; o; o >>= 1) mx = fmaxf(mx, __shfl_xor_sync(0xffffffffu, mx, o));

    float sum = 0.f;
#pragma unroll
    for (int c = 0; c < 8; c++) {
        if (c >= np) break;
        float e0 = __expf(v[2 * c] - mx);
        float e1 = __expf(v[2 * c + 1] - mx);
        v[2 * c] = e0; v[2 * c + 1] = e1;
        sum += e0 + e1;
    }
#pragma unroll
    for (int o = 16; o; o >>= 1) sum += __shfl_xor_sync(0xffffffffu, sum, o);
    float inv = 1.f / sum;

    uint32_t* ph32 = reinterpret_cast<uint32_t*>(p.Ph[part] + (size_t)row * n);
#pragma unroll
    for (int c = 0; c < 8; c++) {
        if (c >= np) break;
        ph32[lane + c * 32] = packhf(__float2half(v[2 * c] * inv),
                                     __float2half(v[2 * c + 1] * inv));
    }
}

// ---------------------------------------------------------------------------
// ctx HMMA (unchanged from R13)
// ---------------------------------------------------------------------------
struct CXP {
    const hf* Ph[2];
    const hf* Vth[2];
    float* O[2];
    int Sq[2], Sk[2];
};

__global__ __launch_bounds__(256) void hmma_ctx_all(CXP p) {
    extern __shared__ __align__(128) char smem[];
    const uint32_t asb = smem_u32(smem);
    const uint32_t bsb = asb + NSTAGE * TILEB;

    const int part = blockIdx.z >> 7;
    const int bh = blockIdx.z & 127, b = bh >> 3, h = bh & 7;
    const int Sq = p.Sq[part], Sk = p.Sk[part];
    const int bm = blockIdx.y * 128;
    if (bm >= Sq) return;
    const int C = Sk / 32;

    const int tid = threadIdx.x;
    const int wid = tid >> 5, lane = tid & 31;
    const int wm = wid >> 2, wn = wid & 3;
    const hf* Ph = p.Ph[part];
    const hf* Vth = p.Vth[part];

    float acc[4][4][4];
#pragma unroll
    for (int i = 0; i < 4; i++)
#pragma unroll
        for (int j = 0; j < 4; j++)
#pragma unroll
            for (int r = 0; r < 4; r++) acc[i][j][r] = 0.f;

    const int r0 = tid >> 2, s0 = (tid & 3);
    const uint32_t a_lm = (uint32_t)((wm * 64 + (lane & 15)) * (PADK * 2) + (lane >> 4) * 16);
    const uint32_t b_lm = (uint32_t)((wn * 32 + (lane & 15)) * (PADK * 2) + (lane >> 4) * 16);

#define CTX_LOAD {                                                             \
        const int kc = c_;                                                     \
        const char* ab = (const char*)(Ph + ((size_t)bh * Sq + bm) * Sk + kc * 32); \
        const char* bb = (const char*)(Vth + (size_t)bh * DD * Sk + kc * 32);  \
        const size_t rs = (size_t)Sk * 2;                                      \
        const uint32_t sa_ = asb + stg_ * TILEB;                               \
        const uint32_t sb_ = bsb + stg_ * TILEB;                               \
        _Pragma("unroll")                                                      \
        for (int u = 0; u < 2; u++) {                                          \
            int row = r0 + u * 64;                                             \
            uint32_t off = (uint32_t)(row * (PADK * 2) + s0 * 16);             \
            cp16(sa_ + off, ab + (size_t)row * rs + s0 * 16);                  \
            cp16(sb_ + off, bb + (size_t)row * rs + s0 * 16);                  \
        }                                                                      \
    }

    MAINLOOP(CTX_LOAD)

    float* O = p.O[part];
#pragma unroll
    for (int i = 0; i < 4; i++) {
#pragma unroll
        for (int j = 0; j < 4; j++) {
            int m = bm + wm * 64 + i * 16 + (lane >> 2);
            int d = wn * 32 + j * 8 + (lane & 3) * 2;
            float2 v0 = make_float2(acc[i][j][0], acc[i][j][1]);
            float2 v1 = make_float2(acc[i][j][2], acc[i][j][3]);
            *reinterpret_cast<float2*>(
                O + ((size_t)(b * Sq + m) * HH + h) * DD + d) = v0;
            *reinterpret_cast<float2*>(
                O + ((size_t)(b * Sq + m + 8) * HH + h) * DD + d) = v1;
        }
    }
}

// ---------------------------------------------------------------------------
extern "C" void kernel_launch(void* const* d_in, const int* in_sizes, int n_in,
                              void* d_out, int out_size) {
    const float* x1    = (const float*)d_in[0];
    const float* mask1 = (const float*)d_in[1];
    const float* x2    = (const float*)d_in[2];
    const float* mask2 = (const float*)d_in[3];
    const float* W1[3] = {(const float*)d_in[4], (const float*)d_in[6], (const float*)d_in[8]};
    const float* b1[3] = {(const float*)d_in[5], (const float*)d_in[7], (const float*)d_in[9]};
    const float* W2[3] = {(const float*)d_in[10], (const float*)d_in[12], (const float*)d_in[14]};
    const float* b2[3] = {(const float*)d_in[11], (const float*)d_in[13], (const float*)d_in[15]};
    float* out = (float*)d_out;

    hf *x1h, *x2h, *w1h, *w2h;
    cudaGetSymbolAddress((void**)&x1h, g_x1h);
    cudaGetSymbolAddress((void**)&x2h, g_x2h);
    cudaGetSymbolAddress((void**)&w1h, g_w1h);
    cudaGetSymbolAddress((void**)&w2h, g_w2h);

    hf *q1h, *k1h, *v1h, *v1th, *q2h, *k2h, *v2h, *v2th;
    cudaGetSymbolAddress((void**)&q1h, g_q1h);
    cudaGetSymbolAddress((void**)&k1h, g_k1h);
    cudaGetSymbolAddress((void**)&v1h, g_v1h);
    cudaGetSymbolAddress((void**)&v1th, g_v1th);
    cudaGetSymbolAddress((void**)&q2h, g_q2h);
    cudaGetSymbolAddress((void**)&k2h, g_k2h);
    cudaGetSymbolAddress((void**)&v2h, g_v2h);
    cudaGetSymbolAddress((void**)&v2th, g_v2th);

    float *p1, *p2;
    hf *p1h, *p2h;
    cudaGetSymbolAddress((void**)&p1, g_p1);
    cudaGetSymbolAddress((void**)&p2, g_p2);
    cudaGetSymbolAddress((void**)&p1h, g_p1h);
    cudaGetSymbolAddress((void**)&p2h, g_p2h);

    cudaFuncSetAttribute(hmma_qkv_all, cudaFuncAttributeMaxDynamicSharedMemorySize, SMEM_DYN);
    cudaFuncSetAttribute(hmma_scores_mc, cudaFuncAttributeMaxDynamicSharedMemorySize, SMEM_DYN);
    cudaFuncSetAttribute(hmma_ctx_all, cudaFuncAttributeMaxDynamicSharedMemorySize, SMEM_DYN);

    const float scale = 1.0f / sqrtf((float)DD);
    dim3 blk(256);

    // 1: merged input converts
    {
        X2 p;
        p.x[0] = (const float4*)x1; p.h[0] = (uint2*)x1h; p.n4[0] = 4096 * 1024 / 4;
        p.x[1] = (const float4*)x2; p.h[1] = (uint2*)x2h; p.n4[1] = 8192 * 768 / 4;
        int gx = (p.n4[1] + 255) / 256;   // larger of the two
        xcvt_all<<<dim3(gx, 2), 256>>>(p);
    }
    // 2: weight converts (transposed)
    {
        WS ws;
        for (int i = 0; i < 3; i++) {
            ws.W[i] = W1[i];
            ws.Wh[i] = w1h + (size_t)i * 1024 * 1024;
            ws.K[i] = 1024;
            ws.W[3 + i] = W2[i];
            ws.Wh[3 + i] = w2h + (size_t)i * 1024 * 768;
            ws.K[3 + i] = 768;
        }
        wsplit_all<<<dim3(32, 32, 6), dim3(32, 8)>>>(ws);
    }

    // 3: all 6 QKV GEMMs
    {
        G6 g;
        for (int i = 0; i < 3; i++) {
            g.A[i] = x1h;
            g.Wh[i] = w1h + (size_t)i * 1024 * 1024;
            g.bias[i] = b1[i];
            g.K[i] = 1024;
            g.M[i] = BB * SS1;
            g.A[3 + i] = x2h;
            g.Wh[3 + i] = w2h + (size_t)i * 1024 * 768;
            g.bias[3 + i] = b2[i];
            g.K[3 + i] = 768;
            g.M[3 + i] = BB * SS2;
        }
        g.out[0] = q1h; g.out[1] = k1h; g.out[2] = v1h;
        g.out[3] = q2h; g.out[4] = k2h; g.out[5] = v2h;
        hmma_qkv_all<<<dim3(8, 64, 6), blk, SMEM_DYN>>>(g);
    }

    // 4: merged V transposes
    {
        VTP p;
        p.V[0] = v1h; p.Vt[0] = v1th; p.S[0] = SS1;
        p.V[1] = v2h; p.Vt[1] = v2th; p.S[1] = SS2;
        vtrans_all<<<dim3(4, 16, 256), dim3(32, 8)>>>(p);
    }

    // 5: Q-resident multi-chunk scores (both directions)
    {
        SCP p;
        p.Qh[0] = q2h; p.Kh[0] = k1h; p.mask[0] = mask1; p.Sout[0] = p1;
        p.Sq[0] = SS2; p.Sk[0] = SS1;
        p.Qh[1] = q1h; p.Kh[1] = k2h; p.mask[1] = mask2; p.Sout[1] = p2;
        p.Sq[1] = SS1; p.Sk[1] = SS2;
        hmma_scores_mc<<<dim3(1, 4, 256), blk, SMEM_DYN>>>(p, scale);
    }

    // 6: merged softmax
    {
        SMP p;
        p.S[0] = p1; p.Ph[0] = p1h; p.n[0] = SS1;
        p.S[1] = p2; p.Ph[1] = p2h; p.n[1] = SS2;
        p.rows0 = BB * HH * SS2;
        int rows_total = BB * HH * SS2 + BB * HH * SS1;
        softmax_all<<<(rows_total + 7) / 8, blk>>>(p, rows_total);
    }

    // 7: merged context (both directions)
    {
        CXP p;
        p.Ph[0] = p1h; p.Vth[0] = v1th; p.O[0] = out;
        p.Sq[0] = SS2; p.Sk[0] = SS1;
        p.Ph[1] = p2h; p.Vth[1] = v2th; p.O[1] = out + C1_ELEMS;
        p.Sq[1] = SS1; p.Sk[1] = SS2;
        hmma_ctx_all<<<dim3(1, 4, 256), blk, SMEM_DYN>>>(p);
    }
}

// round 16
// speedup vs baseline: 1.2354x; 1.0736x over previous
#include <cuda_runtime.h>
#include <cuda_fp16.h>
#include <cstdint>
#include <math.h>

// ===========================================================================
// BertBiAttention on GB300 (sm_103 ptxas target -> mma.sync HMMA everywhere)
//   B=16, S1=256, S2=512, V_HID=1024, T_HID=768, BI_HID=1024, H=8, D=128
// Round 16: R13 structure (best known) with the V transpose kernel DELETED —
//   the QKV epilogue for V slices scatters directly into [B,H,D,S].
//   7 launches. Everything else byte-identical to R13.
// ===========================================================================

#define BB   16
#define SS1  256
#define SS2  512
#define HH   8
#define DD   128
#define HD   1024
#define C1_ELEMS ((size_t)BB * SS2 * HD)

typedef __half hf;

#define PADK 40
#define NSTAGE 4
#define TILEB (128 * PADK * 2)          // 10240 bytes per tile
#define SMEM_DYN (2 * NSTAGE * TILEB)   // 81920 bytes

// ---------------- scratch ----------------
__device__ hf g_x1h[4096 * 1024];
__device__ hf g_x2h[8192 * 768];
__device__ hf g_w1h[3][1024 * 1024];   // transposed [N][K]
__device__ hf g_w2h[3][1024 * 768];

__device__ hf g_q1h[BB * SS1 * HD];
__device__ hf g_k1h[BB * SS1 * HD];
__device__ hf g_v1th[BB * HH * DD * SS1];   // V directly in [B,H,D,S]
__device__ hf g_q2h[BB * SS2 * HD];
__device__ hf g_k2h[BB * SS2 * HD];
__device__ hf g_v2th[BB * HH * DD * SS2];

#define P_ELEMS ((size_t)BB * HH * SS2 * SS1)
__device__ float g_p1[P_ELEMS];
__device__ float g_p2[P_ELEMS];
__device__ hf g_p1h[P_ELEMS];
__device__ hf g_p2h[P_ELEMS];

// ---------------- helpers ----------------
__device__ __forceinline__ uint32_t smem_u32(const void* p) {
    uint32_t a;
    asm("{ .reg .u64 t; cvta.to.shared.u64 t, %1; cvt.u32.u64 %0, t; }"
        : "=r"(a) : "l"(p));
    return a;
}
__device__ __forceinline__ void cp16(uint32_t dst, const void* src) {
    asm volatile("cp.async.cg.shared.global [%0], [%1], 16;\n" :: "r"(dst), "l"(src));
}
__device__ __forceinline__ void ldsm_x4(uint32_t& r0, uint32_t& r1,
                                        uint32_t& r2, uint32_t& r3, uint32_t a) {
    asm volatile("ldmatrix.sync.aligned.m8n8.x4.shared.b16 {%0,%1,%2,%3}, [%4];"
                 : "=r"(r0), "=r"(r1), "=r"(r2), "=r"(r3) : "r"(a));
}
__device__ __forceinline__ void mma16816(float* c, uint32_t a0, uint32_t a1,
                                         uint32_t a2, uint32_t a3,
                                         uint32_t b0, uint32_t b1) {
    asm volatile(
        "mma.sync.aligned.m16n8k16.row.col.f32.f16.f16.f32 "
        "{%0,%1,%2,%3}, {%4,%5,%6,%7}, {%8,%9}, {%0,%1,%2,%3};"
        : "+f"(c[0]), "+f"(c[1]), "+f"(c[2]), "+f"(c[3])
        : "r"(a0), "r"(a1), "r"(a2), "r"(a3), "r"(b0), "r"(b1));
}
__device__ __forceinline__ uint32_t packhf(hf a, hf b) {
    __half2 t = __halves2half2(a, b);
    return *reinterpret_cast<uint32_t*>(&t);
}

// ---------------- convert kernels ----------------
__global__ void xcvt(const float4* __restrict__ x, uint2* __restrict__ h, int n4) {
    int i = blockIdx.x * blockDim.x + threadIdx.x;
    if (i >= n4) return;
    float4 v = x[i];
    uint2 hp;
    hp.x = packhf(__float2half(v.x), __float2half(v.y));
    hp.y = packhf(__float2half(v.z), __float2half(v.w));
    h[i] = hp;
}

struct WS {
    const float* W[6];
    hf* Wh[6];
    int K[6];
};

__global__ void wsplit_all(WS ws) {
    const int z = blockIdx.z;
    const int K = ws.K[z];
    const int N = 1024;
    const int k0 = blockIdx.y * 32, n0 = blockIdx.x * 32;
    if (k0 >= K) return;
    __shared__ float t[32][33];
    const float* W = ws.W[z];
    hf* Wh = ws.Wh[z];
    int tx = threadIdx.x, ty = threadIdx.y;
#pragma unroll
    for (int i = 0; i < 4; i++)
        t[ty + i * 8][tx] = W[(size_t)(k0 + ty + i * 8) * N + n0 + tx];
    __syncthreads();
#pragma unroll
    for (int i = 0; i < 4; i++) {
        float v = t[tx][ty + i * 8];
        size_t o = (size_t)(n0 + ty + i * 8) * K + k0 + tx;
        Wh[o] = __float2half(v);
    }
}

// ===========================================================================
// 4-stage pipelined mainloop
// ===========================================================================

#define MAINLOOP(LOADBODY)                                                     \
    for (int s = 0; s < NSTAGE - 1; ++s) {                                     \
        if (s < C) { const int c_ = s; const int stg_ = s; LOADBODY }          \
        asm volatile("cp.async.commit_group;\n");                              \
    }                                                                          \
    for (int c = 0; c < C; ++c) {                                              \
        asm volatile("cp.async.wait_group %0;\n" :: "n"(NSTAGE - 2));          \
        __syncthreads();                                                       \
        const int buf = c & (NSTAGE - 1);                                      \
        const uint32_t sa = asb + buf * TILEB + a_lm;                          \
        const uint32_t sb2 = bsb + buf * TILEB + b_lm;                         \
        _Pragma("unroll")                                                      \
        for (int kk = 0; kk < 2; kk++) {                                       \
            uint32_t a[4][4], bbf[2][4];                                       \
            _Pragma("unroll")                                                  \
            for (int i = 0; i < 4; i++)                                        \
                ldsm_x4(a[i][0], a[i][1], a[i][2], a[i][3],                    \
                        sa + i * 16 * (PADK * 2) + kk * 32);                   \
            _Pragma("unroll")                                                  \
            for (int j2 = 0; j2 < 2; j2++)                                     \
                ldsm_x4(bbf[j2][0], bbf[j2][1], bbf[j2][2], bbf[j2][3],        \
                        sb2 + j2 * 16 * (PADK * 2) + kk * 32);                 \
            _Pragma("unroll")                                                  \
            for (int i = 0; i < 4; i++)                                        \
                _Pragma("unroll")                                              \
                for (int j = 0; j < 4; j++) {                                  \
                    int j2 = j >> 1, jo = j & 1;                               \
                    mma16816(acc[i][j], a[i][0], a[i][1], a[i][2], a[i][3],    \
                             bbf[j2][jo], bbf[j2][jo + 2]);                    \
                }                                                              \
        }                                                                      \
        if (c + NSTAGE - 1 < C) {                                              \
            const int c_ = c + NSTAGE - 1;                                     \
            const int stg_ = c_ & (NSTAGE - 1);                                \
            LOADBODY                                                           \
        }                                                                      \
        asm volatile("cp.async.commit_group;\n");                              \
    }

// ---------------------------------------------------------------------------
// QKV HMMA GEMM: both streams, one launch; V slices scatter to [B,H,D,S].
// ---------------------------------------------------------------------------
struct G6 {
    const hf* A[6];
    const hf* Wh[6];
    const float* bias[6];
    hf* out[6];
    int K[6];
    int M[6];
    int sshift[6];   // log2(S)
    int isV[6];      // 1 -> out is [B,H,D,S] transposed layout
};

__global__ __launch_bounds__(256) void hmma_qkv_all(G6 g) {
    const int N = 1024;
    extern __shared__ __align__(128) char smem[];
    const uint32_t asb = smem_u32(smem);
    const uint32_t bsb = asb + NSTAGE * TILEB;

    const int z = blockIdx.z;
    const int bm = blockIdx.y * 128;
    if (bm >= g.M[z]) return;
    const int bn = blockIdx.x * 128;
    const int K = g.K[z];
    const int C = K / 32;

    const int tid = threadIdx.x;
    const int wid = tid >> 5, lane = tid & 31;
    const int wm = wid >> 2, wn = wid & 3;
    const hf* Ah = g.A[z];
    const hf* Wh = g.Wh[z];

    float acc[4][4][4];
#pragma unroll
    for (int i = 0; i < 4; i++)
#pragma unroll
        for (int j = 0; j < 4; j++)
#pragma unroll
            for (int r = 0; r < 4; r++) acc[i][j][r] = 0.f;

    const int r0 = tid >> 2, s0 = (tid & 3);
    const uint32_t a_lm = (uint32_t)((wm * 64 + (lane & 15)) * (PADK * 2) + (lane >> 4) * 16);
    const uint32_t b_lm = (uint32_t)((wn * 32 + (lane & 15)) * (PADK * 2) + (lane >> 4) * 16);

#define QKV_LOAD {                                                             \
        const int kc = c_;                                                     \
        const char* ab = (const char*)(Ah + (size_t)bm * K + kc * 32);         \
        const char* bb = (const char*)(Wh + (size_t)bn * K + kc * 32);         \
        const size_t rs = (size_t)K * 2;                                       \
        const uint32_t sa_ = asb + stg_ * TILEB;                               \
        const uint32_t sb_ = bsb + stg_ * TILEB;                               \
        _Pragma("unroll")                                                      \
        for (int u = 0; u < 2; u++) {                                          \
            int row = r0 + u * 64;                                             \
            uint32_t off = (uint32_t)(row * (PADK * 2) + s0 * 16);             \
            cp16(sa_ + off, ab + (size_t)row * rs + s0 * 16);                  \
            cp16(sb_ + off, bb + (size_t)row * rs + s0 * 16);                  \
        }                                                                      \
    }

    MAINLOOP(QKV_LOAD)

    hf* outp = g.out[z];
    const float* bias = g.bias[z];
    if (!g.isV[z]) {
        // q/k: standard [B,S,H,D] fp16 stores
#pragma unroll
        for (int i = 0; i < 4; i++) {
#pragma unroll
            for (int j = 0; j < 4; j++) {
                int m = bm + wm * 64 + i * 16 + (lane >> 2);
                int n = bn + wn * 32 + j * 8 + (lane & 3) * 2;
                float b0 = __ldg(bias + n), b1 = __ldg(bias + n + 1);
                *reinterpret_cast<uint32_t*>(outp + (size_t)m * N + n) =
                    packhf(__float2half(acc[i][j][0] + b0), __float2half(acc[i][j][1] + b1));
                *reinterpret_cast<uint32_t*>(outp + (size_t)(m + 8) * N + n) =
                    packhf(__float2half(acc[i][j][2] + b0), __float2half(acc[i][j][3] + b1));
            }
        }
    } else {
        // V: scatter to [B,H,D,S] (transposed). Tile rows are 128-aligned and
        // S >= 256, so all rows in this tile share one batch index.
        const int sshift = g.sshift[z];
        const int S = 1 << sshift;
        const int bidx = bm >> sshift;
#pragma unroll
        for (int i = 0; i < 4; i++) {
#pragma unroll
            for (int j = 0; j < 4; j++) {
                int m = bm + wm * 64 + i * 16 + (lane >> 2);
                int s = m & (S - 1);
                int n = bn + wn * 32 + j * 8 + (lane & 3) * 2;
                float b0 = __ldg(bias + n), b1 = __ldg(bias + n + 1);
                int h = n >> 7, d = n & 127;
                size_t base = (((size_t)(bidx * HH + h)) * DD + d) * S + s;
                outp[base]         = __float2half(acc[i][j][0] + b0);
                outp[base + S]     = __float2half(acc[i][j][1] + b1);
                outp[base + 8]     = __float2half(acc[i][j][2] + b0);
                outp[base + S + 8] = __float2half(acc[i][j][3] + b1);
            }
        }
    }
}

// ---------------------------------------------------------------------------
// scores HMMA (R13 version): both directions, one launch.
// ---------------------------------------------------------------------------
struct SCP {
    const hf* Qh[2];
    const hf* Kh[2];
    const float* mask[2];
    float* Sout[2];
    int Sq[2], Sk[2];
};

__global__ __launch_bounds__(256) void hmma_scores_all(SCP p, float scale) {
    extern __shared__ __align__(128) char smem[];
    const uint32_t asb = smem_u32(smem);
    const uint32_t bsb = asb + NSTAGE * TILEB;

    const int part = blockIdx.z >> 7;
    const int bh = blockIdx.z & 127, b = bh >> 3, h = bh & 7;
    const int Sq = p.Sq[part], Sk = p.Sk[part];
    const int bm = blockIdx.y * 128;
    if (bm >= Sq) return;
    const int bn = blockIdx.x * 128;
    if (bn >= Sk) return;
    const int C = 4;

    const int tid = threadIdx.x;
    const int wid = tid >> 5, lane = tid & 31;
    const int wm = wid >> 2, wn = wid & 3;
    const hf* Qh = p.Qh[part];
    const hf* Kh = p.Kh[part];

    float acc[4][4][4];
#pragma unroll
    for (int i = 0; i < 4; i++)
#pragma unroll
        for (int j = 0; j < 4; j++)
#pragma unroll
            for (int r = 0; r < 4; r++) acc[i][j][r] = 0.f;

    const int r0 = tid >> 2, s0 = (tid & 3);
    const uint32_t a_lm = (uint32_t)((wm * 64 + (lane & 15)) * (PADK * 2) + (lane >> 4) * 16);
    const uint32_t b_lm = (uint32_t)((wn * 32 + (lane & 15)) * (PADK * 2) + (lane >> 4) * 16);

#define SC_LOAD {                                                              \
        const int kc = c_;                                                     \
        const char* ab = (const char*)(Qh + (size_t)(b * Sq + bm) * HD + h * DD + kc * 32); \
        const char* bb = (const char*)(Kh + (size_t)(b * Sk + bn) * HD + h * DD + kc * 32); \
        const size_t rs = (size_t)HD * 2;                                      \
        const uint32_t sa_ = asb + stg_ * TILEB;                               \
        const uint32_t sb_ = bsb + stg_ * TILEB;                               \
        _Pragma("unroll")                                                      \
        for (int u = 0; u < 2; u++) {                                          \
            int row = r0 + u * 64;                                             \
            uint32_t off = (uint32_t)(row * (PADK * 2) + s0 * 16);             \
            cp16(sa_ + off, ab + (size_t)row * rs + s0 * 16);                  \
            cp16(sb_ + off, bb + (size_t)row * rs + s0 * 16);                  \
        }                                                                      \
    }

    MAINLOOP(SC_LOAD)

    float* Sout = p.Sout[part];
    const float* mask = p.mask[part];
#pragma unroll
    for (int i = 0; i < 4; i++) {
#pragma unroll
        for (int j = 0; j < 4; j++) {
            int m = bm + wm * 64 + i * 16 + (lane >> 2);
            int n = bn + wn * 32 + j * 8 + (lane & 3) * 2;
            float mk0 = __ldg(mask + b * Sk + n);
            float mk1 = __ldg(mask + b * Sk + n + 1);
            float2 v0 = make_float2(acc[i][j][0] * scale + mk0,
                                    acc[i][j][1] * scale + mk1);
            float2 v1 = make_float2(acc[i][j][2] * scale + mk0,
                                    acc[i][j][3] * scale + mk1);
            *reinterpret_cast<float2*>(Sout + ((size_t)bh * Sq + m) * Sk + n) = v0;
            *reinterpret_cast<float2*>(Sout + ((size_t)bh * Sq + m + 8) * Sk + n) = v1;
        }
    }
}

// ---------------------------------------------------------------------------
// softmax -> fp16 P (unchanged)
// ---------------------------------------------------------------------------
struct SMP {
    const float* S[2];
    hf* Ph[2];
    int rows0;
    int n[2];
};

__global__ __launch_bounds__(256) void softmax_all(SMP p, int rows_total) {
    int rg = (blockIdx.x * blockDim.x + threadIdx.x) >> 5;
    int lane = threadIdx.x & 31;
    if (rg >= rows_total) return;
    int part = (rg < p.rows0) ? 0 : 1;
    int row = (part == 0) ? rg : rg - p.rows0;
    const int n = p.n[part];
    const float2* r2 = reinterpret_cast<const float2*>(p.S[part] + (size_t)row * n);
    const int np = n >> 6;

    float v[16];
    float mx = -INFINITY;
#pragma unroll
    for (int c = 0; c < 8; c++) {
        if (c >= np) break;
        float2 t = r2[lane + c * 32];
        v[2 * c] = t.x; v[2 * c + 1] = t.y;
        mx = fmaxf(mx, fmaxf(t.x, t.y));
    }
#pragma unroll
    for (int o = 16; o; o >>= 1) mx = fmaxf(mx, __shfl_xor_sync(0xffffffffu, mx, o));

    float sum = 0.f;
#pragma unroll
    for (int c = 0; c < 8; c++) {
        if (c >= np) break;
        float e0 = __expf(v[2 * c] - mx);
        float e1 = __expf(v[2 * c + 1] - mx);
        v[2 * c] = e0; v[2 * c + 1] = e1;
        sum += e0 + e1;
    }
#pragma unroll
    for (int o = 16; o; o >>= 1) sum += __shfl_xor_sync(0xffffffffu, sum, o);
    float inv = 1.f / sum;

    uint32_t* ph32 = reinterpret_cast<uint32_t*>(p.Ph[part] + (size_t)row * n);
#pragma unroll
    for (int c = 0; c < 8; c++) {
        if (c >= np) break;
        ph32[lane + c * 32] = packhf(__float2half(v[2 * c] * inv),
                                     __float2half(v[2 * c + 1] * inv));
    }
}

// ---------------------------------------------------------------------------
// ctx HMMA (unchanged)
// ---------------------------------------------------------------------------
struct CXP {
    const hf* Ph[2];
    const hf* Vth[2];
    float* O[2];
    int Sq[2], Sk[2];
};

__global__ __launch_bounds__(256) void hmma_ctx_all(CXP p) {
    extern __shared__ __align__(128) char smem[];
    const uint32_t asb = smem_u32(smem);
    const uint32_t bsb = asb + NSTAGE * TILEB;

    const int part = blockIdx.z >> 7;
    const int bh = blockIdx.z & 127, b = bh >> 3, h = bh & 7;
    const int Sq = p.Sq[part], Sk = p.Sk[part];
    const int bm = blockIdx.y * 128;
    if (bm >= Sq) return;
    const int C = Sk / 32;

    const int tid = threadIdx.x;
    const int wid = tid >> 5, lane = tid & 31;
    const int wm = wid >> 2, wn = wid & 3;
    const hf* Ph = p.Ph[part];
    const hf* Vth = p.Vth[part];

    float acc[4][4][4];
#pragma unroll
    for (int i = 0; i < 4; i++)
#pragma unroll
        for (int j = 0; j < 4; j++)
#pragma unroll
            for (int r = 0; r < 4; r++) acc[i][j][r] = 0.f;

    const int r0 = tid >> 2, s0 = (tid & 3);
    const uint32_t a_lm = (uint32_t)((wm * 64 + (lane & 15)) * (PADK * 2) + (lane >> 4) * 16);
    const uint32_t b_lm = (uint32_t)((wn * 32 + (lane & 15)) * (PADK * 2) + (lane >> 4) * 16);

#define CTX_LOAD {                                                             \
        const int kc = c_;                                                     \
        const char* ab = (const char*)(Ph + ((size_t)bh * Sq + bm) * Sk + kc * 32); \
        const char* bb = (const char*)(Vth + (size_t)bh * DD * Sk + kc * 32);  \
        const size_t rs = (size_t)Sk * 2;                                      \
        const uint32_t sa_ = asb + stg_ * TILEB;                               \
        const uint32_t sb_ = bsb + stg_ * TILEB;                               \
        _Pragma("unroll")                                                      \
        for (int u = 0; u < 2; u++) {                                          \
            int row = r0 + u * 64;                                             \
            uint32_t off = (uint32_t)(row * (PADK * 2) + s0 * 16);             \
            cp16(sa_ + off, ab + (size_t)row * rs + s0 * 16);                  \
            cp16(sb_ + off, bb + (size_t)row * rs + s0 * 16);                  \
        }                                                                      \
    }

    MAINLOOP(CTX_LOAD)

    float* O = p.O[part];
#pragma unroll
    for (int i = 0; i < 4; i++) {
#pragma unroll
        for (int j = 0; j < 4; j++) {
            int m = bm + wm * 64 + i * 16 + (lane >> 2);
            int d = wn * 32 + j * 8 + (lane & 3) * 2;
            float2 v0 = make_float2(acc[i][j][0], acc[i][j][1]);
            float2 v1 = make_float2(acc[i][j][2], acc[i][j][3]);
            *reinterpret_cast<float2*>(
                O + ((size_t)(b * Sq + m) * HH + h) * DD + d) = v0;
            *reinterpret_cast<float2*>(
                O + ((size_t)(b * Sq + m + 8) * HH + h) * DD + d) = v1;
        }
    }
}

// ---------------------------------------------------------------------------
extern "C" void kernel_launch(void* const* d_in, const int* in_sizes, int n_in,
                              void* d_out, int out_size) {
    const float* x1    = (const float*)d_in[0];
    const float* mask1 = (const float*)d_in[1];
    const float* x2    = (const float*)d_in[2];
    const float* mask2 = (const float*)d_in[3];
    const float* W1[3] = {(const float*)d_in[4], (const float*)d_in[6], (const float*)d_in[8]};
    const float* b1[3] = {(const float*)d_in[5], (const float*)d_in[7], (const float*)d_in[9]};
    const float* W2[3] = {(const float*)d_in[10], (const float*)d_in[12], (const float*)d_in[14]};
    const float* b2[3] = {(const float*)d_in[11], (const float*)d_in[13], (const float*)d_in[15]};
    float* out = (float*)d_out;

    hf *x1h, *x2h, *w1h, *w2h;
    cudaGetSymbolAddress((void**)&x1h, g_x1h);
    cudaGetSymbolAddress((void**)&x2h, g_x2h);
    cudaGetSymbolAddress((void**)&w1h, g_w1h);
    cudaGetSymbolAddress((void**)&w2h, g_w2h);

    hf *q1h, *k1h, *v1th, *q2h, *k2h, *v2th;
    cudaGetSymbolAddress((void**)&q1h, g_q1h);
    cudaGetSymbolAddress((void**)&k1h, g_k1h);
    cudaGetSymbolAddress((void**)&v1th, g_v1th);
    cudaGetSymbolAddress((void**)&q2h, g_q2h);
    cudaGetSymbolAddress((void**)&k2h, g_k2h);
    cudaGetSymbolAddress((void**)&v2th, g_v2th);

    float *p1, *p2;
    hf *p1h, *p2h;
    cudaGetSymbolAddress((void**)&p1, g_p1);
    cudaGetSymbolAddress((void**)&p2, g_p2);
    cudaGetSymbolAddress((void**)&p1h, g_p1h);
    cudaGetSymbolAddress((void**)&p2h, g_p2h);

    cudaFuncSetAttribute(hmma_qkv_all, cudaFuncAttributeMaxDynamicSharedMemorySize, SMEM_DYN);
    cudaFuncSetAttribute(hmma_scores_all, cudaFuncAttributeMaxDynamicSharedMemorySize, SMEM_DYN);
    cudaFuncSetAttribute(hmma_ctx_all, cudaFuncAttributeMaxDynamicSharedMemorySize, SMEM_DYN);

    const float scale = 1.0f / sqrtf((float)DD);
    dim3 blk(256);

    // 1-2: input converts
    {
        int n4 = 4096 * 1024 / 4;
        xcvt<<<n4 / 256, 256>>>((const float4*)x1, (uint2*)x1h, n4);
    }
    {
        int n4 = 8192 * 768 / 4;
        xcvt<<<n4 / 256, 256>>>((const float4*)x2, (uint2*)x2h, n4);
    }
    // 3: weight converts (transposed)
    {
        WS ws;
        for (int i = 0; i < 3; i++) {
            ws.W[i] = W1[i];
            ws.Wh[i] = w1h + (size_t)i * 1024 * 1024;
            ws.K[i] = 1024;
            ws.W[3 + i] = W2[i];
            ws.Wh[3 + i] = w2h + (size_t)i * 1024 * 768;
            ws.K[3 + i] = 768;
        }
        wsplit_all<<<dim3(32, 32, 6), dim3(32, 8)>>>(ws);
    }

    // 4: all 6 QKV GEMMs; V slices write [B,H,D,S] directly
    {
        G6 g;
        for (int i = 0; i < 3; i++) {
            g.A[i] = x1h;
            g.Wh[i] = w1h + (size_t)i * 1024 * 1024;
            g.bias[i] = b1[i];
            g.K[i] = 1024;
            g.M[i] = BB * SS1;
            g.sshift[i] = 8;
            g.isV[i] = (i == 2);
            g.A[3 + i] = x2h;
            g.Wh[3 + i] = w2h + (size_t)i * 1024 * 768;
            g.bias[3 + i] = b2[i];
            g.K[3 + i] = 768;
            g.M[3 + i] = BB * SS2;
            g.sshift[3 + i] = 9;
            g.isV[3 + i] = (i == 2);
        }
        g.out[0] = q1h; g.out[1] = k1h; g.out[2] = v1th;
        g.out[3] = q2h; g.out[4] = k2h; g.out[5] = v2th;
        hmma_qkv_all<<<dim3(8, 64, 6), blk, SMEM_DYN>>>(g);
    }

    // 5: merged scores (both directions)
    {
        SCP p;
        p.Qh[0] = q2h; p.Kh[0] = k1h; p.mask[0] = mask1; p.Sout[0] = p1;
        p.Sq[0] = SS2; p.Sk[0] = SS1;
        p.Qh[1] = q1h; p.Kh[1] = k2h; p.mask[1] = mask2; p.Sout[1] = p2;
        p.Sq[1] = SS1; p.Sk[1] = SS2;
        hmma_scores_all<<<dim3(4, 4, 256), blk, SMEM_DYN>>>(p, scale);
    }

    // 6: merged softmax
    {
        SMP p;
        p.S[0] = p1; p.Ph[0] = p1h; p.n[0] = SS1;
        p.S[1] = p2; p.Ph[1] = p2h; p.n[1] = SS2;
        p.rows0 = BB * HH * SS2;
        int rows_total = BB * HH * SS2 + BB * HH * SS1;
        softmax_all<<<(rows_total + 7) / 8, blk>>>(p, rows_total);
    }

    // 7: merged context (both directions)
    {
        CXP p;
        p.Ph[0] = p1h; p.Vth[0] = v1th; p.O[0] = out;
        p.Sq[0] = SS2; p.Sk[0] = SS1;
        p.Ph[1] = p2h; p.Vth[1] = v2th; p.O[1] = out + C1_ELEMS;
        p.Sq[1] = SS1; p.Sk[1] = SS2;
        hmma_ctx_all<<<dim3(1, 4, 256), blk, SMEM_DYN>>>(p);
    }
}

// round 17
// speedup vs baseline: 1.3988x; 1.1322x over previous
#include <cuda_runtime.h>
#include <cuda_fp16.h>
#include <cstdint>
#include <math.h>

// ===========================================================================
// BertBiAttention on GB300 (sm_103 ptxas target -> mma.sync HMMA everywhere)
//   B=16, S1=256, S2=512, V_HID=1024, T_HID=768, BI_HID=1024, H=8, D=128
// Round 17: softmax kernel DELETED via shift-invariance:
//   scores epilogue writes e = exp(s*scale+mask) as fp16 (unnormalized);
//   ctx accumulates row sums from its smem A tiles and scales O by 1/rowsum.
//   6 launches. QKV path unchanged from R16 (V scatters to [B,H,D,S]).
// ===========================================================================

#define BB   16
#define SS1  256
#define SS2  512
#define HH   8
#define DD   128
#define HD   1024
#define C1_ELEMS ((size_t)BB * SS2 * HD)

typedef __half hf;

#define PADK 40
#define NSTAGE 4
#define TILEB (128 * PADK * 2)          // 10240 bytes per tile
#define SMEM_DYN (2 * NSTAGE * TILEB)   // 81920 bytes
#define SMEM_CTX (SMEM_DYN + 1024)      // + rowsum partials (256 fp32)

// ---------------- scratch ----------------
__device__ hf g_x1h[4096 * 1024];
__device__ hf g_x2h[8192 * 768];
__device__ hf g_w1h[3][1024 * 1024];   // transposed [N][K]
__device__ hf g_w2h[3][1024 * 768];

__device__ hf g_q1h[BB * SS1 * HD];
__device__ hf g_k1h[BB * SS1 * HD];
__device__ hf g_v1th[BB * HH * DD * SS1];   // V in [B,H,D,S]
__device__ hf g_q2h[BB * SS2 * HD];
__device__ hf g_k2h[BB * SS2 * HD];
__device__ hf g_v2th[BB * HH * DD * SS2];

#define P_ELEMS ((size_t)BB * HH * SS2 * SS1)
__device__ hf g_p1h[P_ELEMS];   // unnormalized exp scores, fp16
__device__ hf g_p2h[P_ELEMS];

// ---------------- helpers ----------------
__device__ __forceinline__ uint32_t smem_u32(const void* p) {
    uint32_t a;
    asm("{ .reg .u64 t; cvta.to.shared.u64 t, %1; cvt.u32.u64 %0, t; }"
        : "=r"(a) : "l"(p));
    return a;
}
__device__ __forceinline__ void cp16(uint32_t dst, const void* src) {
    asm volatile("cp.async.cg.shared.global [%0], [%1], 16;\n" :: "r"(dst), "l"(src));
}
__device__ __forceinline__ void ldsm_x4(uint32_t& r0, uint32_t& r1,
                                        uint32_t& r2, uint32_t& r3, uint32_t a) {
    asm volatile("ldmatrix.sync.aligned.m8n8.x4.shared.b16 {%0,%1,%2,%3}, [%4];"
                 : "=r"(r0), "=r"(r1), "=r"(r2), "=r"(r3) : "r"(a));
}
__device__ __forceinline__ void mma16816(float* c, uint32_t a0, uint32_t a1,
                                         uint32_t a2, uint32_t a3,
                                         uint32_t b0, uint32_t b1) {
    asm volatile(
        "mma.sync.aligned.m16n8k16.row.col.f32.f16.f16.f32 "
        "{%0,%1,%2,%3}, {%4,%5,%6,%7}, {%8,%9}, {%0,%1,%2,%3};"
        : "+f"(c[0]), "+f"(c[1]), "+f"(c[2]), "+f"(c[3])
        : "r"(a0), "r"(a1), "r"(a2), "r"(a3), "r"(b0), "r"(b1));
}
__device__ __forceinline__ uint32_t packhf(hf a, hf b) {
    __half2 t = __halves2half2(a, b);
    return *reinterpret_cast<uint32_t*>(&t);
}

// ---------------- convert kernels ----------------
__global__ void xcvt(const float4* __restrict__ x, uint2* __restrict__ h, int n4) {
    int i = blockIdx.x * blockDim.x + threadIdx.x;
    if (i >= n4) return;
    float4 v = x[i];
    uint2 hp;
    hp.x = packhf(__float2half(v.x), __float2half(v.y));
    hp.y = packhf(__float2half(v.z), __float2half(v.w));
    h[i] = hp;
}

struct WS {
    const float* W[6];
    hf* Wh[6];
    int K[6];
};

__global__ void wsplit_all(WS ws) {
    const int z = blockIdx.z;
    const int K = ws.K[z];
    const int N = 1024;
    const int k0 = blockIdx.y * 32, n0 = blockIdx.x * 32;
    if (k0 >= K) return;
    __shared__ float t[32][33];
    const float* W = ws.W[z];
    hf* Wh = ws.Wh[z];
    int tx = threadIdx.x, ty = threadIdx.y;
#pragma unroll
    for (int i = 0; i < 4; i++)
        t[ty + i * 8][tx] = W[(size_t)(k0 + ty + i * 8) * N + n0 + tx];
    __syncthreads();
#pragma unroll
    for (int i = 0; i < 4; i++) {
        float v = t[tx][ty + i * 8];
        size_t o = (size_t)(n0 + ty + i * 8) * K + k0 + tx;
        Wh[o] = __float2half(v);
    }
}

// ===========================================================================
// 4-stage pipelined mainloop
// ===========================================================================

#define MAINLOOP(LOADBODY)                                                     \
    for (int s = 0; s < NSTAGE - 1; ++s) {                                     \
        if (s < C) { const int c_ = s; const int stg_ = s; LOADBODY }          \
        asm volatile("cp.async.commit_group;\n");                              \
    }                                                                          \
    for (int c = 0; c < C; ++c) {                                              \
        asm volatile("cp.async.wait_group %0;\n" :: "n"(NSTAGE - 2));          \
        __syncthreads();                                                       \
        const int buf = c & (NSTAGE - 1);                                      \
        const uint32_t sa = asb + buf * TILEB + a_lm;                          \
        const uint32_t sb2 = bsb + buf * TILEB + b_lm;                         \
        _Pragma("unroll")                                                      \
        for (int kk = 0; kk < 2; kk++) {                                       \
            uint32_t a[4][4], bbf[2][4];                                       \
            _Pragma("unroll")                                                  \
            for (int i = 0; i < 4; i++)                                        \
                ldsm_x4(a[i][0], a[i][1], a[i][2], a[i][3],                    \
                        sa + i * 16 * (PADK * 2) + kk * 32);                   \
            _Pragma("unroll")                                                  \
            for (int j2 = 0; j2 < 2; j2++)                                     \
                ldsm_x4(bbf[j2][0], bbf[j2][1], bbf[j2][2], bbf[j2][3],        \
                        sb2 + j2 * 16 * (PADK * 2) + kk * 32);                 \
            _Pragma("unroll")                                                  \
            for (int i = 0; i < 4; i++)                                        \
                _Pragma("unroll")                                              \
                for (int j = 0; j < 4; j++) {                                  \
                    int j2 = j >> 1, jo = j & 1;                               \
                    mma16816(acc[i][j], a[i][0], a[i][1], a[i][2], a[i][3],    \
                             bbf[j2][jo], bbf[j2][jo + 2]);                    \
                }                                                              \
        }                                                                      \
        if (c + NSTAGE - 1 < C) {                                              \
            const int c_ = c + NSTAGE - 1;                                     \
            const int stg_ = c_ & (NSTAGE - 1);                                \
            LOADBODY                                                           \
        }                                                                      \
        asm volatile("cp.async.commit_group;\n");                              \
    }

// ---------------------------------------------------------------------------
// QKV HMMA GEMM (unchanged from R16)
// ---------------------------------------------------------------------------
struct G6 {
    const hf* A[6];
    const hf* Wh[6];
    const float* bias[6];
    hf* out[6];
    int K[6];
    int M[6];
    int sshift[6];
    int isV[6];
};

__global__ __launch_bounds__(256) void hmma_qkv_all(G6 g) {
    const int N = 1024;
    extern __shared__ __align__(128) char smem[];
    const uint32_t asb = smem_u32(smem);
    const uint32_t bsb = asb + NSTAGE * TILEB;

    const int z = blockIdx.z;
    const int bm = blockIdx.y * 128;
    if (bm >= g.M[z]) return;
    const int bn = blockIdx.x * 128;
    const int K = g.K[z];
    const int C = K / 32;

    const int tid = threadIdx.x;
    const int wid = tid >> 5, lane = tid & 31;
    const int wm = wid >> 2, wn = wid & 3;
    const hf* Ah = g.A[z];
    const hf* Wh = g.Wh[z];

    float acc[4][4][4];
#pragma unroll
    for (int i = 0; i < 4; i++)
#pragma unroll
        for (int j = 0; j < 4; j++)
#pragma unroll
            for (int r = 0; r < 4; r++) acc[i][j][r] = 0.f;

    const int r0 = tid >> 2, s0 = (tid & 3);
    const uint32_t a_lm = (uint32_t)((wm * 64 + (lane & 15)) * (PADK * 2) + (lane >> 4) * 16);
    const uint32_t b_lm = (uint32_t)((wn * 32 + (lane & 15)) * (PADK * 2) + (lane >> 4) * 16);

#define QKV_LOAD {                                                             \
        const int kc = c_;                                                     \
        const char* ab = (const char*)(Ah + (size_t)bm * K + kc * 32);         \
        const char* bb = (const char*)(Wh + (size_t)bn * K + kc * 32);         \
        const size_t rs = (size_t)K * 2;                                       \
        const uint32_t sa_ = asb + stg_ * TILEB;                               \
        const uint32_t sb_ = bsb + stg_ * TILEB;                               \
        _Pragma("unroll")                                                      \
        for (int u = 0; u < 2; u++) {                                          \
            int row = r0 + u * 64;                                             \
            uint32_t off = (uint32_t)(row * (PADK * 2) + s0 * 16);             \
            cp16(sa_ + off, ab + (size_t)row * rs + s0 * 16);                  \
            cp16(sb_ + off, bb + (size_t)row * rs + s0 * 16);                  \
        }                                                                      \
    }

    MAINLOOP(QKV_LOAD)

    hf* outp = g.out[z];
    const float* bias = g.bias[z];
    if (!g.isV[z]) {
#pragma unroll
        for (int i = 0; i < 4; i++) {
#pragma unroll
            for (int j = 0; j < 4; j++) {
                int m = bm + wm * 64 + i * 16 + (lane >> 2);
                int n = bn + wn * 32 + j * 8 + (lane & 3) * 2;
                float b0 = __ldg(bias + n), b1 = __ldg(bias + n + 1);
                *reinterpret_cast<uint32_t*>(outp + (size_t)m * N + n) =
                    packhf(__float2half(acc[i][j][0] + b0), __float2half(acc[i][j][1] + b1));
                *reinterpret_cast<uint32_t*>(outp + (size_t)(m + 8) * N + n) =
                    packhf(__float2half(acc[i][j][2] + b0), __float2half(acc[i][j][3] + b1));
            }
        }
    } else {
        const int sshift = g.sshift[z];
        const int S = 1 << sshift;
        const int bidx = bm >> sshift;
#pragma unroll
        for (int i = 0; i < 4; i++) {
#pragma unroll
            for (int j = 0; j < 4; j++) {
                int m = bm + wm * 64 + i * 16 + (lane >> 2);
                int s = m & (S - 1);
                int n = bn + wn * 32 + j * 8 + (lane & 3) * 2;
                float b0 = __ldg(bias + n), b1 = __ldg(bias + n + 1);
                int h = n >> 7, d = n & 127;
                size_t base = (((size_t)(bidx * HH + h)) * DD + d) * S + s;
                outp[base]         = __float2half(acc[i][j][0] + b0);
                outp[base + S]     = __float2half(acc[i][j][1] + b1);
                outp[base + 8]     = __float2half(acc[i][j][2] + b0);
                outp[base + S + 8] = __float2half(acc[i][j][3] + b1);
            }
        }
    }
}

// ---------------------------------------------------------------------------
// scores HMMA: epilogue writes e = exp(s*scale + mask) as fp16 (unnormalized)
// ---------------------------------------------------------------------------
struct SCP {
    const hf* Qh[2];
    const hf* Kh[2];
    const float* mask[2];
    hf* Eout[2];
    int Sq[2], Sk[2];
};

__global__ __launch_bounds__(256) void hmma_scores_all(SCP p, float scale) {
    extern __shared__ __align__(128) char smem[];
    const uint32_t asb = smem_u32(smem);
    const uint32_t bsb = asb + NSTAGE * TILEB;

    const int part = blockIdx.z >> 7;
    const int bh = blockIdx.z & 127, b = bh >> 3, h = bh & 7;
    const int Sq = p.Sq[part], Sk = p.Sk[part];
    const int bm = blockIdx.y * 128;
    if (bm >= Sq) return;
    const int bn = blockIdx.x * 128;
    if (bn >= Sk) return;
    const int C = 4;

    const int tid = threadIdx.x;
    const int wid = tid >> 5, lane = tid & 31;
    const int wm = wid >> 2, wn = wid & 3;
    const hf* Qh = p.Qh[part];
    const hf* Kh = p.Kh[part];

    float acc[4][4][4];
#pragma unroll
    for (int i = 0; i < 4; i++)
#pragma unroll
        for (int j = 0; j < 4; j++)
#pragma unroll
            for (int r = 0; r < 4; r++) acc[i][j][r] = 0.f;

    const int r0 = tid >> 2, s0 = (tid & 3);
    const uint32_t a_lm = (uint32_t)((wm * 64 + (lane & 15)) * (PADK * 2) + (lane >> 4) * 16);
    const uint32_t b_lm = (uint32_t)((wn * 32 + (lane & 15)) * (PADK * 2) + (lane >> 4) * 16);

#define SC_LOAD {                                                              \
        const int kc = c_;                                                     \
        const char* ab = (const char*)(Qh + (size_t)(b * Sq + bm) * HD + h * DD + kc * 32); \
        const char* bb = (const char*)(Kh + (size_t)(b * Sk + bn) * HD + h * DD + kc * 32); \
        const size_t rs = (size_t)HD * 2;                                      \
        const uint32_t sa_ = asb + stg_ * TILEB;                               \
        const uint32_t sb_ = bsb + stg_ * TILEB;                               \
        _Pragma("unroll")                                                      \
        for (int u = 0; u < 2; u++) {                                          \
            int row = r0 + u * 64;                                             \
            uint32_t off = (uint32_t)(row * (PADK * 2) + s0 * 16);             \
            cp16(sa_ + off, ab + (size_t)row * rs + s0 * 16);                  \
            cp16(sb_ + off, bb + (size_t)row * rs + s0 * 16);                  \
        }                                                                      \
    }

    MAINLOOP(SC_LOAD)

    hf* Eout = p.Eout[part];
    const float* mask = p.mask[part];
#pragma unroll
    for (int i = 0; i < 4; i++) {
#pragma unroll
        for (int j = 0; j < 4; j++) {
            int m = bm + wm * 64 + i * 16 + (lane >> 2);
            int n = bn + wn * 32 + j * 8 + (lane & 3) * 2;
            float mk0 = __ldg(mask + b * Sk + n);
            float mk1 = __ldg(mask + b * Sk + n + 1);
            float e0 = __expf(acc[i][j][0] * scale + mk0);
            float e1 = __expf(acc[i][j][1] * scale + mk1);
            float e2 = __expf(acc[i][j][2] * scale + mk0);
            float e3 = __expf(acc[i][j][3] * scale + mk1);
            *reinterpret_cast<uint32_t*>(Eout + ((size_t)bh * Sq + m) * Sk + n) =
                packhf(__float2half(e0), __float2half(e1));
            *reinterpret_cast<uint32_t*>(Eout + ((size_t)bh * Sq + m + 8) * Sk + n) =
                packhf(__float2half(e2), __float2half(e3));
        }
    }
}

// ---------------------------------------------------------------------------
// ctx HMMA: O = (E @ V) / rowsum(E).  Row sums accumulated from the smem A
// tiles as they stream (deterministic), epilogue scales by 1/rowsum.
// ---------------------------------------------------------------------------
struct CXP {
    const hf* Eh[2];
    const hf* Vth[2];
    float* O[2];
    int Sq[2], Sk[2];
};

__global__ __launch_bounds__(256) void hmma_ctx_all(CXP p) {
    extern __shared__ __align__(128) char smem[];
    const uint32_t asb = smem_u32(smem);
    const uint32_t bsb = asb + NSTAGE * TILEB;
    float* red = (float*)(smem + SMEM_DYN);   // 256 fp32 partials

    const int part = blockIdx.z >> 7;
    const int bh = blockIdx.z & 127, b = bh >> 3, h = bh & 7;
    const int Sq = p.Sq[part], Sk = p.Sk[part];
    const int bm = blockIdx.y * 128;
    if (bm >= Sq) return;
    const int C = Sk / 32;

    const int tid = threadIdx.x;
    const int wid = tid >> 5, lane = tid & 31;
    const int wm = wid >> 2, wn = wid & 3;
    const hf* Eh = p.Eh[part];
    const hf* Vth = p.Vth[part];

    float acc[4][4][4];
#pragma unroll
    for (int i = 0; i < 4; i++)
#pragma unroll
        for (int j = 0; j < 4; j++)
#pragma unroll
            for (int r = 0; r < 4; r++) acc[i][j][r] = 0.f;

    const int r0 = tid >> 2, s0 = (tid & 3);
    const uint32_t a_lm = (uint32_t)((wm * 64 + (lane & 15)) * (PADK * 2) + (lane >> 4) * 16);
    const uint32_t b_lm = (uint32_t)((wn * 32 + (lane & 15)) * (PADK * 2) + (lane >> 4) * 16);

    // rowsum accumulation assignment: thread t -> row t>>1, 16 cols (t&1)
    const int sr_row = tid >> 1, sr_half = tid & 1;
    float rsum = 0.f;

#define CTX_LOAD {                                                             \
        const int kc = c_;                                                     \
        const char* ab = (const char*)(Eh + ((size_t)bh * Sq + bm) * Sk + kc * 32); \
        const char* bb = (const char*)(Vth + (size_t)bh * DD * Sk + kc * 32);  \
        const size_t rs = (size_t)Sk * 2;                                      \
        const uint32_t sa_ = asb + stg_ * TILEB;                               \
        const uint32_t sb_ = bsb + stg_ * TILEB;                               \
        _Pragma("unroll")                                                      \
        for (int u = 0; u < 2; u++) {                                          \
            int row = r0 + u * 64;                                             \
            uint32_t off = (uint32_t)(row * (PADK * 2) + s0 * 16);             \
            cp16(sa_ + off, ab + (size_t)row * rs + s0 * 16);                  \
            cp16(sb_ + off, bb + (size_t)row * rs + s0 * 16);                  \
        }                                                                      \
    }

    // custom mainloop (MAINLOOP + rowsum block)
    for (int s = 0; s < NSTAGE - 1; ++s) {
        if (s < C) { const int c_ = s; const int stg_ = s; CTX_LOAD }
        asm volatile("cp.async.commit_group;\n");
    }
    for (int c = 0; c < C; ++c) {
        asm volatile("cp.async.wait_group %0;\n" :: "n"(NSTAGE - 2));
        __syncthreads();
        const int buf = c & (NSTAGE - 1);
        const uint32_t sa = asb + buf * TILEB + a_lm;
        const uint32_t sb2 = bsb + buf * TILEB + b_lm;

        // rowsum: sum this A tile (128 rows x 32 cols of e, fp16)
        {
            const uint32_t rbase = asb + buf * TILEB + sr_row * (PADK * 2) + sr_half * 32;
            float2 part2 = make_float2(0.f, 0.f);
#pragma unroll
            for (int k = 0; k < 8; k++) {
                uint32_t w;
                asm volatile("ld.shared.b32 %0, [%1];" : "=r"(w) : "r"(rbase + k * 4));
                __half2 h2 = *reinterpret_cast<__half2*>(&w);
                float2 f2 = __half22float2(h2);
                part2.x += f2.x; part2.y += f2.y;
            }
            rsum += part2.x + part2.y;
        }

#pragma unroll
        for (int kk = 0; kk < 2; kk++) {
            uint32_t a[4][4], bbf[2][4];
#pragma unroll
            for (int i = 0; i < 4; i++)
                ldsm_x4(a[i][0], a[i][1], a[i][2], a[i][3],
                        sa + i * 16 * (PADK * 2) + kk * 32);
#pragma unroll
            for (int j2 = 0; j2 < 2; j2++)
                ldsm_x4(bbf[j2][0], bbf[j2][1], bbf[j2][2], bbf[j2][3],
                        sb2 + j2 * 16 * (PADK * 2) + kk * 32);
#pragma unroll
            for (int i = 0; i < 4; i++)
#pragma unroll
                for (int j = 0; j < 4; j++) {
                    int j2 = j >> 1, jo = j & 1;
                    mma16816(acc[i][j], a[i][0], a[i][1], a[i][2], a[i][3],
                             bbf[j2][jo], bbf[j2][jo + 2]);
                }
        }
        if (c + NSTAGE - 1 < C) {
            const int c_ = c + NSTAGE - 1;
            const int stg_ = c_ & (NSTAGE - 1);
            CTX_LOAD
        }
        asm volatile("cp.async.commit_group;\n");
    }

    // finalize row sums
    red[tid] = rsum;
    __syncthreads();

    float* O = p.O[part];
#pragma unroll
    for (int i = 0; i < 4; i++) {
        int mrow = wm * 64 + i * 16 + (lane >> 2);
        float invA = 1.f / (red[2 * mrow] + red[2 * mrow + 1]);
        float invB = 1.f / (red[2 * (mrow + 8)] + red[2 * (mrow + 8) + 1]);
        int m = bm + mrow;
#pragma unroll
        for (int j = 0; j < 4; j++) {
            int d = wn * 32 + j * 8 + (lane & 3) * 2;
            float2 v0 = make_float2(acc[i][j][0] * invA, acc[i][j][1] * invA);
            float2 v1 = make_float2(acc[i][j][2] * invB, acc[i][j][3] * invB);
            *reinterpret_cast<float2*>(
                O + ((size_t)(b * Sq + m) * HH + h) * DD + d) = v0;
            *reinterpret_cast<float2*>(
                O + ((size_t)(b * Sq + m + 8) * HH + h) * DD + d) = v1;
        }
    }
}

// ---------------------------------------------------------------------------
extern "C" void kernel_launch(void* const* d_in, const int* in_sizes, int n_in,
                              void* d_out, int out_size) {
    const float* x1    = (const float*)d_in[0];
    const float* mask1 = (const float*)d_in[1];
    const float* x2    = (const float*)d_in[2];
    const float* mask2 = (const float*)d_in[3];
    const float* W1[3] = {(const float*)d_in[4], (const float*)d_in[6], (const float*)d_in[8]};
    const float* b1[3] = {(const float*)d_in[5], (const float*)d_in[7], (const float*)d_in[9]};
    const float* W2[3] = {(const float*)d_in[10], (const float*)d_in[12], (const float*)d_in[14]};
    const float* b2[3] = {(const float*)d_in[11], (const float*)d_in[13], (const float*)d_in[15]};
    float* out = (float*)d_out;

    hf *x1h, *x2h, *w1h, *w2h;
    cudaGetSymbolAddress((void**)&x1h, g_x1h);
    cudaGetSymbolAddress((void**)&x2h, g_x2h);
    cudaGetSymbolAddress((void**)&w1h, g_w1h);
    cudaGetSymbolAddress((void**)&w2h, g_w2h);

    hf *q1h, *k1h, *v1th, *q2h, *k2h, *v2th;
    cudaGetSymbolAddress((void**)&q1h, g_q1h);
    cudaGetSymbolAddress((void**)&k1h, g_k1h);
    cudaGetSymbolAddress((void**)&v1th, g_v1th);
    cudaGetSymbolAddress((void**)&q2h, g_q2h);
    cudaGetSymbolAddress((void**)&k2h, g_k2h);
    cudaGetSymbolAddress((void**)&v2th, g_v2th);

    hf *p1h, *p2h;
    cudaGetSymbolAddress((void**)&p1h, g_p1h);
    cudaGetSymbolAddress((void**)&p2h, g_p2h);

    cudaFuncSetAttribute(hmma_qkv_all, cudaFuncAttributeMaxDynamicSharedMemorySize, SMEM_DYN);
    cudaFuncSetAttribute(hmma_scores_all, cudaFuncAttributeMaxDynamicSharedMemorySize, SMEM_DYN);
    cudaFuncSetAttribute(hmma_ctx_all, cudaFuncAttributeMaxDynamicSharedMemorySize, SMEM_CTX);

    const float scale = 1.0f / sqrtf((float)DD);
    dim3 blk(256);

    // 1-2: input converts
    {
        int n4 = 4096 * 1024 / 4;
        xcvt<<<n4 / 256, 256>>>((const float4*)x1, (uint2*)x1h, n4);
    }
    {
        int n4 = 8192 * 768 / 4;
        xcvt<<<n4 / 256, 256>>>((const float4*)x2, (uint2*)x2h, n4);
    }
    // 3: weight converts (transposed)
    {
        WS ws;
        for (int i = 0; i < 3; i++) {
            ws.W[i] = W1[i];
            ws.Wh[i] = w1h + (size_t)i * 1024 * 1024;
            ws.K[i] = 1024;
            ws.W[3 + i] = W2[i];
            ws.Wh[3 + i] = w2h + (size_t)i * 1024 * 768;
            ws.K[3 + i] = 768;
        }
        wsplit_all<<<dim3(32, 32, 6), dim3(32, 8)>>>(ws);
    }

    // 4: all 6 QKV GEMMs; V slices write [B,H,D,S] directly
    {
        G6 g;
        for (int i = 0; i < 3; i++) {
            g.A[i] = x1h;
            g.Wh[i] = w1h + (size_t)i * 1024 * 1024;
            g.bias[i] = b1[i];
            g.K[i] = 1024;
            g.M[i] = BB * SS1;
            g.sshift[i] = 8;
            g.isV[i] = (i == 2);
            g.A[3 + i] = x2h;
            g.Wh[3 + i] = w2h + (size_t)i * 1024 * 768;
            g.bias[3 + i] = b2[i];
            g.K[3 + i] = 768;
            g.M[3 + i] = BB * SS2;
            g.sshift[3 + i] = 9;
            g.isV[3 + i] = (i == 2);
        }
        g.out[0] = q1h; g.out[1] = k1h; g.out[2] = v1th;
        g.out[3] = q2h; g.out[4] = k2h; g.out[5] = v2th;
        hmma_qkv_all<<<dim3(8, 64, 6), blk, SMEM_DYN>>>(g);
    }

    // 5: merged scores -> unnormalized exp, fp16
    {
        SCP p;
        p.Qh[0] = q2h; p.Kh[0] = k1h; p.mask[0] = mask1; p.Eout[0] = p1h;
        p.Sq[0] = SS2; p.Sk[0] = SS1;
        p.Qh[1] = q1h; p.Kh[1] = k2h; p.mask[1] = mask2; p.Eout[1] = p2h;
        p.Sq[1] = SS1; p.Sk[1] = SS2;
        hmma_scores_all<<<dim3(4, 4, 256), blk, SMEM_DYN>>>(p, scale);
    }

    // 6: merged context with in-kernel row-sum normalization
    {
        CXP p;
        p.Eh[0] = p1h; p.Vth[0] = v1th; p.O[0] = out;
        p.Sq[0] = SS2; p.Sk[0] = SS1;
        p.Eh[1] = p2h; p.Vth[1] = v2th; p.O[1] = out + C1_ELEMS;
        p.Sq[1] = SS1; p.Sk[1] = SS2;
        hmma_ctx_all<<<dim3(1, 4, 256), blk, SMEM_CTX>>>(p);
    }
}